// round 11
// baseline (speedup 1.0000x reference)
#include <cuda_runtime.h>
#include <cuda_bf16.h>
#include <mma.h>
#include <math.h>
#include <stdint.h>

using namespace nvcuda;

#define D_MODEL 1024
#define HEADS   16
#define DKH     64
#define D_FF    4096
#define BATCH   2
#define SEQ     2048
#define MROWS   (BATCH * SEQ)   // 4096
#define EPS_LN  1e-6f
#define NELEM   (MROWS * D_MODEL)
#define WELEM   (D_MODEL * D_MODEL)
#define FELEM   (D_FF * D_MODEL)
#define FFELEM  (MROWS * D_FF)

// ---------------- scratch (static device globals; no allocs) ----------------
__device__ __nv_bfloat16 g_xh[NELEM],  g_xl[NELEM];
__device__ __nv_bfloat16 g_wqh[WELEM], g_wql[WELEM];
__device__ __nv_bfloat16 g_wkh[WELEM], g_wkl[WELEM];
__device__ __nv_bfloat16 g_wvh[WELEM], g_wvl[WELEM];
__device__ __nv_bfloat16 g_woh[WELEM], g_wol[WELEM];
__device__ __nv_bfloat16 g_w1h[FELEM], g_w1l[FELEM];
__device__ __nv_bfloat16 g_w2h[FELEM], g_w2l[FELEM];
__device__ __nv_bfloat16 g_qh[NELEM],  g_ql[NELEM];
__device__ __nv_bfloat16 g_kh[NELEM],  g_kl[NELEM];
__device__ __nv_bfloat16 g_vh[NELEM],  g_vl[NELEM];
__device__ __nv_bfloat16 g_ah[NELEM],  g_al[NELEM];
__device__ __nv_bfloat16 g_r1h[NELEM], g_r1l[NELEM];
__device__ __nv_bfloat16 g_ffh[FFELEM], g_ffl[FFELEM];
__device__ float g_tmp[NELEM];
__device__ float g_r1f[NELEM];
__device__ float g_tmp2[NELEM];

// ================= helpers ===================================================
__device__ __forceinline__ void split2(float a, float b, uint32_t& hi, uint32_t& lo) {
    __nv_bfloat16 ha = __float2bfloat16_rn(a);
    __nv_bfloat16 hb = __float2bfloat16_rn(b);
    float la = a - __bfloat162float(ha);
    float lb = b - __bfloat162float(hb);
    __nv_bfloat162 hv = __halves2bfloat162(ha, hb);
    __nv_bfloat162 lv = __floats2bfloat162_rn(la, lb);
    hi = *reinterpret_cast<uint32_t*>(&hv);
    lo = *reinterpret_cast<uint32_t*>(&lv);
}

#define CP16(dst, src) \
    asm volatile("cp.async.cg.shared.global [%0], [%1], 16;" :: \
        "r"((uint32_t)__cvta_generic_to_shared(dst)), "l"(src))
#define CP_COMMIT() asm volatile("cp.async.commit_group;" ::: "memory")
#define CP_WAIT(n)  asm volatile("cp.async.wait_group %0;" :: "n"(n) : "memory")

// ---------------- fp32 -> bf16 hi/lo conversion ------------------------------
__global__ __launch_bounds__(256)
void cvt_hl(const float* __restrict__ src, __nv_bfloat16* __restrict__ hi,
            __nv_bfloat16* __restrict__ lo, int n4)
{
    int i = blockIdx.x * 256 + threadIdx.x;
    if (i < n4) {
        float4 v = ((const float4*)src)[i];
        uint32_t h01, l01, h23, l23;
        split2(v.x, v.y, h01, l01);
        split2(v.z, v.w, h23, l23);
        ((uint2*)hi)[i] = make_uint2(h01, h23);
        ((uint2*)lo)[i] = make_uint2(l01, l23);
    }
}

// ================= WMMA GEMM: C = A @ B^T (+epilogue), bf16x3 ================
// block 256x128, 8 warps (4m x 2n), warp tile 64x64 (AI: 48 flop/smem-byte).
// k-chunk 32, 2-stage cp.async pipeline.
// EPI: 0 none, 1 relu, 2 residual. OUT: 0 fp32, 1 bf16 hi/lo. QKV: fused 3-dest.
#define GLDT    40
#define ATILE   (256 * GLDT)                 // 10240 elems
#define BTILE   (128 * GLDT)                 // 5120 elems
#define GSTAGE  (2 * ATILE + 2 * BTILE)      // 30720 elems
#define GSTAGES 2
#define GEMM_SMEM (GSTAGES * GSTAGE * 2)     // 122880 B

__device__ __forceinline__ void gemm_issue(__nv_bfloat16* st,
    const __nv_bfloat16* Ahg, const __nv_bfloat16* Alg,
    const __nv_bfloat16* Bhg, const __nv_bfloat16* Blg,
    int K, int k0, int tid)
{
    __nv_bfloat16* sAh = st;
    __nv_bfloat16* sAl = st + ATILE;
    __nv_bfloat16* sBh = st + 2 * ATILE;
    __nv_bfloat16* sBl = st + 2 * ATILE + BTILE;
    // A: 256 rows x 32 cols -> 1024 16B chunks per tile
#pragma unroll
    for (int it = 0; it < 4; it++) {
        int ch = tid + it * 256;
        int r = ch >> 2;
        int c = (ch & 3) * 8;
        CP16(sAh + r * GLDT + c, Ahg + (size_t)r * K + k0 + c);
        CP16(sAl + r * GLDT + c, Alg + (size_t)r * K + k0 + c);
    }
    // B: 128 rows x 32 cols -> 512 chunks per tile
#pragma unroll
    for (int it = 0; it < 2; it++) {
        int ch = tid + it * 256;
        int r = ch >> 2;
        int c = (ch & 3) * 8;
        CP16(sBh + r * GLDT + c, Bhg + (size_t)r * K + k0 + c);
        CP16(sBl + r * GLDT + c, Blg + (size_t)r * K + k0 + c);
    }
}

template <int EPI, int OUT, int QKV>
__global__ __launch_bounds__(256)
void gemm_bf(const __nv_bfloat16* __restrict__ Ah, const __nv_bfloat16* __restrict__ Al,
             const __nv_bfloat16* __restrict__ Bh_, const __nv_bfloat16* __restrict__ Bl_,
             const __nv_bfloat16* __restrict__ Bh2, const __nv_bfloat16* __restrict__ Bl2,
             const __nv_bfloat16* __restrict__ Bh3, const __nv_bfloat16* __restrict__ Bl3,
             const float* __restrict__ Rf, float* __restrict__ Cf,
             __nv_bfloat16* __restrict__ Ch_, __nv_bfloat16* __restrict__ Cl_,
             __nv_bfloat16* __restrict__ Ch2, __nv_bfloat16* __restrict__ Cl2,
             __nv_bfloat16* __restrict__ Ch3, __nv_bfloat16* __restrict__ Cl3,
             int M, int N, int K)
{
    extern __shared__ __nv_bfloat16 sh[];

    const int tid = threadIdx.x;
    const int wid = tid >> 5;
    const int wm = (wid & 3) * 64;        // 4 m-warps, 64 rows each
    const int wn = (wid >> 2) * 64;       // 2 n-warps, 64 cols each

    const __nv_bfloat16* Bh = Bh_;
    const __nv_bfloat16* Bl = Bl_;
    __nv_bfloat16* Ch = Ch_;
    __nv_bfloat16* Cl = Cl_;
    int col0;
    if (QKV) {
        const int mat = blockIdx.x >> 3;      // 0,1,2 -> q,k,v
        col0 = (blockIdx.x & 7) * 128;
        if (mat == 1) { Bh = Bh2; Bl = Bl2; Ch = Ch2; Cl = Cl2; }
        else if (mat == 2) { Bh = Bh3; Bl = Bl3; Ch = Ch3; Cl = Cl3; }
    } else {
        col0 = blockIdx.x * 128;
    }
    const int row0 = blockIdx.y * 256;
    const __nv_bfloat16* Ahg = Ah + (size_t)row0 * K;
    const __nv_bfloat16* Alg = Al + (size_t)row0 * K;
    const __nv_bfloat16* Bhg = Bh + (size_t)col0 * K;
    const __nv_bfloat16* Blg = Bl + (size_t)col0 * K;

    wmma::fragment<wmma::accumulator, 16, 16, 16, float> acc[4][4];
#pragma unroll
    for (int i = 0; i < 4; i++)
#pragma unroll
        for (int j = 0; j < 4; j++) wmma::fill_fragment(acc[i][j], 0.f);

    const int T = K / 32;
    gemm_issue(sh, Ahg, Alg, Bhg, Blg, K, 0, tid);
    CP_COMMIT();

    for (int t = 0; t < T; t++) {
        CP_WAIT(0);
        __syncthreads();
        if (t + 1 < T) {
            gemm_issue(sh + ((t + 1) & 1) * GSTAGE, Ahg, Alg, Bhg, Blg,
                       K, (t + 1) * 32, tid);
            CP_COMMIT();
        }
        __nv_bfloat16* Ahs = sh + (t & 1) * GSTAGE;
        __nv_bfloat16* Als = Ahs + ATILE;
        __nv_bfloat16* Bhs = Ahs + 2 * ATILE;
        __nv_bfloat16* Bls = Ahs + 2 * ATILE + BTILE;
#pragma unroll
        for (int ks = 0; ks < 32; ks += 16) {
            wmma::fragment<wmma::matrix_a, 16, 16, 16, __nv_bfloat16, wmma::row_major> a_hi[4], a_lo[4];
#pragma unroll
            for (int i = 0; i < 4; i++) {
                wmma::load_matrix_sync(a_hi[i], Ahs + (wm + i * 16) * GLDT + ks, GLDT);
                wmma::load_matrix_sync(a_lo[i], Als + (wm + i * 16) * GLDT + ks, GLDT);
            }
#pragma unroll
            for (int j = 0; j < 4; j++) {
                wmma::fragment<wmma::matrix_b, 16, 16, 16, __nv_bfloat16, wmma::col_major> b_hi, b_lo;
                wmma::load_matrix_sync(b_hi, Bhs + (wn + j * 16) * GLDT + ks, GLDT);
                wmma::load_matrix_sync(b_lo, Bls + (wn + j * 16) * GLDT + ks, GLDT);
#pragma unroll
                for (int i = 0; i < 4; i++) {
                    wmma::mma_sync(acc[i][j], a_hi[i], b_hi, acc[i][j]);
                    wmma::mma_sync(acc[i][j], a_hi[i], b_lo, acc[i][j]);
                    wmma::mma_sync(acc[i][j], a_lo[i], b_hi, acc[i][j]);
                }
            }
        }
        __syncthreads();
    }

    if (OUT == 0) {
#pragma unroll
        for (int i = 0; i < 4; i++) {
#pragma unroll
            for (int j = 0; j < 4; j++) {
                const int row = row0 + wm + i * 16;
                const int col = col0 + wn + j * 16;
                if (EPI == 2) {
                    wmma::fragment<wmma::accumulator, 16, 16, 16, float> rf;
                    wmma::load_matrix_sync(rf, Rf + (size_t)row * N + col, N, wmma::mem_row_major);
#pragma unroll
                    for (int e = 0; e < rf.num_elements; e++) acc[i][j].x[e] += rf.x[e];
                }
                if (EPI == 1) {
#pragma unroll
                    for (int e = 0; e < acc[i][j].num_elements; e++)
                        acc[i][j].x[e] = fmaxf(acc[i][j].x[e], 0.f);
                }
                wmma::store_matrix_sync(Cf + (size_t)row * N + col, acc[i][j], N, wmma::mem_row_major);
            }
        }
    } else {
        // bf16 hi/lo out: stage 256x68 fp32 in smem, two column groups
        float* stg = (float*)sh;              // 256*68*4 = 69632 B <= 122880
        const int wnidx = wid >> 2;
#pragma unroll
        for (int g = 0; g < 2; g++) {
            __syncthreads();
#pragma unroll
            for (int i = 0; i < 4; i++) {
#pragma unroll
                for (int jj = 0; jj < 2; jj++) {
                    const int j = 2 * g + jj;
                    if (EPI == 1) {
#pragma unroll
                        for (int e = 0; e < acc[i][j].num_elements; e++)
                            acc[i][j].x[e] = fmaxf(acc[i][j].x[e], 0.f);
                    }
                    wmma::store_matrix_sync(stg + (wm + i * 16) * 68 + wnidx * 32 + jj * 16,
                                            acc[i][j], 68, wmma::mem_row_major);
                }
            }
            __syncthreads();
            const int r = tid;                 // 256 threads, one row each
#pragma unroll
            for (int p = 0; p < 4; p++) {
                const int gcol = col0 + (p >> 1) * 64 + g * 32 + (p & 1) * 16;
                const size_t off = (size_t)(row0 + r) * N + gcol;
#pragma unroll
                for (int q = 0; q < 16; q += 4) {
                    float4 v = *(const float4*)(stg + r * 68 + p * 16 + q);
                    uint32_t h01, l01, h23, l23;
                    split2(v.x, v.y, h01, l01);
                    split2(v.z, v.w, h23, l23);
                    *(uint2*)(Ch + off + q) = make_uint2(h01, h23);
                    *(uint2*)(Cl + off + q) = make_uint2(l01, l23);
                }
            }
        }
    }
}

// ================= WMMA flash attention (bf16x3 in/out, fp32 softmax) ========
#define LDH 72
#define LDF 68
#define FO_QH 0
#define FO_QL (FO_QH + 128 * LDH * 2)
#define FO_KH (FO_QL + 128 * LDH * 2)
#define FO_KL (FO_KH + 64 * LDH * 2)
#define FO_VH (FO_KL + 64 * LDH * 2)
#define FO_VL (FO_VH + 64 * LDH * 2)
#define FO_PH (FO_VL + 64 * LDH * 2)
#define FO_PL (FO_PH + 128 * LDH * 2)
#define FO_SF (FO_PL + 128 * LDH * 2)
#define FO_MR (FO_SF + 128 * LDF * 4)
#define FO_LR (FO_MR + 512)
#define FO_CR (FO_LR + 512)
#define FA_SMEM (FO_CR + 512)             // 146944 B

__global__ __launch_bounds__(512)
void flash_bf(const __nv_bfloat16* __restrict__ Qh_g, const __nv_bfloat16* __restrict__ Ql_g,
              const __nv_bfloat16* __restrict__ Kh_g, const __nv_bfloat16* __restrict__ Kl_g,
              const __nv_bfloat16* __restrict__ Vh_g, const __nv_bfloat16* __restrict__ Vl_g,
              __nv_bfloat16* __restrict__ Oh_g, __nv_bfloat16* __restrict__ Ol_g)
{
    extern __shared__ char fsm[];
    __nv_bfloat16* Qh = (__nv_bfloat16*)(fsm + FO_QH);
    __nv_bfloat16* Ql = (__nv_bfloat16*)(fsm + FO_QL);
    __nv_bfloat16* Kh = (__nv_bfloat16*)(fsm + FO_KH);
    __nv_bfloat16* Kl = (__nv_bfloat16*)(fsm + FO_KL);
    __nv_bfloat16* Vh = (__nv_bfloat16*)(fsm + FO_VH);
    __nv_bfloat16* Vl = (__nv_bfloat16*)(fsm + FO_VL);
    __nv_bfloat16* Ph = (__nv_bfloat16*)(fsm + FO_PH);
    __nv_bfloat16* Pl = (__nv_bfloat16*)(fsm + FO_PL);
    float* Sf   = (float*)(fsm + FO_SF);
    float* mrow = (float*)(fsm + FO_MR);
    float* lrow = (float*)(fsm + FO_LR);
    float* crow = (float*)(fsm + FO_CR);

    const int qb = gridDim.x - 1 - blockIdx.x;   // heavy q-blocks first
    const int h = blockIdx.y, bb = blockIdx.z;
    const int tid = threadIdx.x;
    const int wid = tid >> 5;
    const int wm = (wid & 3) * 32;
    const int wn = (wid >> 2) * 16;
    const int q0 = qb * 128;
    const size_t base = (size_t)bb * SEQ * D_MODEL + (size_t)h * DKH;

    const int r  = tid >> 2;
    const int c0 = (tid & 3) * 16;

    {
        const size_t g = base + (size_t)(q0 + r) * D_MODEL + c0;
        *(uint4*)(Qh + r * LDH + c0)     = *(const uint4*)(Qh_g + g);
        *(uint4*)(Qh + r * LDH + c0 + 8) = *(const uint4*)(Qh_g + g + 8);
        *(uint4*)(Ql + r * LDH + c0)     = *(const uint4*)(Ql_g + g);
        *(uint4*)(Ql + r * LDH + c0 + 8) = *(const uint4*)(Ql_g + g + 8);
    }
    if (tid < 128) { mrow[tid] = -INFINITY; lrow[tid] = 0.f; }

    float orow[16];
#pragma unroll
    for (int j = 0; j < 16; j++) orow[j] = 0.f;
    __syncthreads();

    const int kmax = 2 * qb + 1;
    for (int kb = 0; kb <= kmax; kb++) {
        const int k0 = kb * 64;

        {
            const int kr = tid >> 3;
            const int kc = (tid & 7) * 8;
            const size_t g = base + (size_t)(k0 + kr) * D_MODEL + kc;
            *(uint4*)(Kh + kr * LDH + kc) = *(const uint4*)(Kh_g + g);
            *(uint4*)(Kl + kr * LDH + kc) = *(const uint4*)(Kl_g + g);
            *(uint4*)(Vh + kr * LDH + kc) = *(const uint4*)(Vh_g + g);
            *(uint4*)(Vl + kr * LDH + kc) = *(const uint4*)(Vl_g + g);
        }
        __syncthreads();

        {
            wmma::fragment<wmma::accumulator, 16, 16, 16, float> accS[2];
#pragma unroll
            for (int i = 0; i < 2; i++) wmma::fill_fragment(accS[i], 0.f);
#pragma unroll
            for (int ks = 0; ks < 64; ks += 16) {
                wmma::fragment<wmma::matrix_a, 16, 16, 16, __nv_bfloat16, wmma::row_major> ah[2], al[2];
                wmma::fragment<wmma::matrix_b, 16, 16, 16, __nv_bfloat16, wmma::col_major> bh, bl;
#pragma unroll
                for (int i = 0; i < 2; i++) {
                    wmma::load_matrix_sync(ah[i], Qh + (wm + i * 16) * LDH + ks, LDH);
                    wmma::load_matrix_sync(al[i], Ql + (wm + i * 16) * LDH + ks, LDH);
                }
                wmma::load_matrix_sync(bh, Kh + wn * LDH + ks, LDH);
                wmma::load_matrix_sync(bl, Kl + wn * LDH + ks, LDH);
#pragma unroll
                for (int i = 0; i < 2; i++) {
                    wmma::mma_sync(accS[i], ah[i], bh, accS[i]);
                    wmma::mma_sync(accS[i], ah[i], bl, accS[i]);
                    wmma::mma_sync(accS[i], al[i], bh, accS[i]);
                }
            }
#pragma unroll
            for (int i = 0; i < 2; i++)
                wmma::store_matrix_sync(Sf + (wm + i * 16) * LDF + wn, accS[i], LDF, wmma::mem_row_major);
        }
        __syncthreads();

        {
            const bool needmask = (k0 + 63 > q0);
            const int qrow = q0 + r;
            float sv[16];
            const float* srow = Sf + r * LDF + c0;
            float mx = -INFINITY;
#pragma unroll
            for (int j = 0; j < 16; j++) {
                float v = srow[j] * 0.125f;
                if (needmask && (k0 + c0 + j) > qrow) v = -INFINITY;
                sv[j] = v;
                mx = fmaxf(mx, v);
            }
            mx = fmaxf(mx, __shfl_xor_sync(0xFFFFFFFFu, mx, 1));
            mx = fmaxf(mx, __shfl_xor_sync(0xFFFFFFFFu, mx, 2));
            const float mold = mrow[r];
            const float mnew = fmaxf(mold, mx);
            float lsum = 0.f;
#pragma unroll
            for (int j = 0; j < 16; j++) {
                float p = __expf(sv[j] - mnew);
                sv[j] = p;
                lsum += p;
            }
            lsum += __shfl_xor_sync(0xFFFFFFFFu, lsum, 1);
            lsum += __shfl_xor_sync(0xFFFFFFFFu, lsum, 2);
#pragma unroll
            for (int j = 0; j < 16; j += 2) {
                uint32_t hv, lv;
                split2(sv[j], sv[j + 1], hv, lv);
                *(uint32_t*)(Ph + r * LDH + c0 + j) = hv;
                *(uint32_t*)(Pl + r * LDH + c0 + j) = lv;
            }
            if ((tid & 3) == 0) {
                const float corr = __expf(mold - mnew);
                mrow[r] = mnew;
                lrow[r] = lrow[r] * corr + lsum;
                crow[r] = corr;
            }
        }
        __syncthreads();

        {
            wmma::fragment<wmma::accumulator, 16, 16, 16, float> accO[2];
#pragma unroll
            for (int i = 0; i < 2; i++) wmma::fill_fragment(accO[i], 0.f);
#pragma unroll
            for (int ks = 0; ks < 64; ks += 16) {
                wmma::fragment<wmma::matrix_a, 16, 16, 16, __nv_bfloat16, wmma::row_major> ah[2], al[2];
                wmma::fragment<wmma::matrix_b, 16, 16, 16, __nv_bfloat16, wmma::row_major> bh, bl;
#pragma unroll
                for (int i = 0; i < 2; i++) {
                    wmma::load_matrix_sync(ah[i], Ph + (wm + i * 16) * LDH + ks, LDH);
                    wmma::load_matrix_sync(al[i], Pl + (wm + i * 16) * LDH + ks, LDH);
                }
                wmma::load_matrix_sync(bh, Vh + ks * LDH + wn, LDH);
                wmma::load_matrix_sync(bl, Vl + ks * LDH + wn, LDH);
#pragma unroll
                for (int i = 0; i < 2; i++) {
                    wmma::mma_sync(accO[i], ah[i], bh, accO[i]);
                    wmma::mma_sync(accO[i], ah[i], bl, accO[i]);
                    wmma::mma_sync(accO[i], al[i], bh, accO[i]);
                }
            }
#pragma unroll
            for (int i = 0; i < 2; i++)
                wmma::store_matrix_sync(Sf + (wm + i * 16) * LDF + wn, accO[i], LDF, wmma::mem_row_major);
        }
        __syncthreads();

        {
            const float corr = crow[r];
            const float* prow = Sf + r * LDF + c0;
#pragma unroll
            for (int j = 0; j < 16; j++) orow[j] = orow[j] * corr + prow[j];
        }
        __syncthreads();
    }

    {
        const float inv = 1.f / lrow[r];
        const size_t g = base + (size_t)(q0 + r) * D_MODEL + c0;
#pragma unroll
        for (int j = 0; j < 16; j += 2) {
            uint32_t hv, lv;
            split2(orow[j] * inv, orow[j + 1] * inv, hv, lv);
            *(uint32_t*)(Oh_g + g + j) = hv;
            *(uint32_t*)(Ol_g + g + j) = lv;
        }
    }
}

// ---------------- LayerNorm (ddof=1), optional hi/lo output ------------------
template <bool HL>
__global__ __launch_bounds__(256)
void layernorm_k(const float* __restrict__ in, const float* __restrict__ gamma,
                 const float* __restrict__ beta, float* __restrict__ out,
                 __nv_bfloat16* __restrict__ oh, __nv_bfloat16* __restrict__ ol)
{
    const int row = blockIdx.x;
    const int tid = threadIdx.x;
    const float4 v = ((const float4*)(in + (size_t)row * D_MODEL))[tid];
    float s  = v.x + v.y + v.z + v.w;
    float ss = v.x * v.x + v.y * v.y + v.z * v.z + v.w * v.w;

    __shared__ float rs[8], rss[8];
#pragma unroll
    for (int o = 16; o > 0; o >>= 1) {
        s  += __shfl_down_sync(0xFFFFFFFFu, s, o);
        ss += __shfl_down_sync(0xFFFFFFFFu, ss, o);
    }
    if ((tid & 31) == 0) { rs[tid >> 5] = s; rss[tid >> 5] = ss; }
    __syncthreads();
    float S = 0.f, SS = 0.f;
#pragma unroll
    for (int i = 0; i < 8; i++) { S += rs[i]; SS += rss[i]; }

    const float mean = S * (1.f / (float)D_MODEL);
    const float var  = (SS - (float)D_MODEL * mean * mean) * (1.f / (float)(D_MODEL - 1));
    const float inv  = rsqrtf(var + EPS_LN);

    const float4 g = ((const float4*)gamma)[tid];
    const float4 b = ((const float4*)beta)[tid];
    float4 o;
    o.x = g.x * (v.x - mean) * inv + b.x;
    o.y = g.y * (v.y - mean) * inv + b.y;
    o.z = g.z * (v.z - mean) * inv + b.z;
    o.w = g.w * (v.w - mean) * inv + b.w;
    ((float4*)(out + (size_t)row * D_MODEL))[tid] = o;
    if (HL) {
        uint32_t h01, l01, h23, l23;
        split2(o.x, o.y, h01, l01);
        split2(o.z, o.w, h23, l23);
        ((uint2*)(oh + (size_t)row * D_MODEL))[tid] = make_uint2(h01, h23);
        ((uint2*)(ol + (size_t)row * D_MODEL))[tid] = make_uint2(l01, l23);
    }
}

// ---------------- host launcher ---------------------------------------------
extern "C" void kernel_launch(void* const* d_in, const int* in_sizes, int n_in,
                              void* d_out, int out_size)
{
    (void)in_sizes; (void)n_in; (void)out_size;
    const float* x  = (const float*)d_in[0];
    const float* Wq = (const float*)d_in[2];
    const float* Wk = (const float*)d_in[3];
    const float* Wv = (const float*)d_in[4];
    const float* Wo = (const float*)d_in[5];
    const float* W1 = (const float*)d_in[6];
    const float* W2 = (const float*)d_in[7];
    const float* g1 = (const float*)d_in[8];
    const float* b1 = (const float*)d_in[9];
    const float* g2 = (const float*)d_in[10];
    const float* b2 = (const float*)d_in[11];
    float* out = (float*)d_out;

    __nv_bfloat16 *xh, *xl, *wqh, *wql, *wkh, *wkl, *wvh, *wvl, *woh, *wol;
    __nv_bfloat16 *w1h, *w1l, *w2h, *w2l;
    __nv_bfloat16 *qh, *ql, *kh, *kl, *vh, *vl, *ah, *al, *r1h, *r1l, *ffh, *ffl;
    float *tmp, *r1f, *tmp2;
    cudaGetSymbolAddress((void**)&xh, g_xh);   cudaGetSymbolAddress((void**)&xl, g_xl);
    cudaGetSymbolAddress((void**)&wqh, g_wqh); cudaGetSymbolAddress((void**)&wql, g_wql);
    cudaGetSymbolAddress((void**)&wkh, g_wkh); cudaGetSymbolAddress((void**)&wkl, g_wkl);
    cudaGetSymbolAddress((void**)&wvh, g_wvh); cudaGetSymbolAddress((void**)&wvl, g_wvl);
    cudaGetSymbolAddress((void**)&woh, g_woh); cudaGetSymbolAddress((void**)&wol, g_wol);
    cudaGetSymbolAddress((void**)&w1h, g_w1h); cudaGetSymbolAddress((void**)&w1l, g_w1l);
    cudaGetSymbolAddress((void**)&w2h, g_w2h); cudaGetSymbolAddress((void**)&w2l, g_w2l);
    cudaGetSymbolAddress((void**)&qh, g_qh);   cudaGetSymbolAddress((void**)&ql, g_ql);
    cudaGetSymbolAddress((void**)&kh, g_kh);   cudaGetSymbolAddress((void**)&kl, g_kl);
    cudaGetSymbolAddress((void**)&vh, g_vh);   cudaGetSymbolAddress((void**)&vl, g_vl);
    cudaGetSymbolAddress((void**)&ah, g_ah);   cudaGetSymbolAddress((void**)&al, g_al);
    cudaGetSymbolAddress((void**)&r1h, g_r1h); cudaGetSymbolAddress((void**)&r1l, g_r1l);
    cudaGetSymbolAddress((void**)&ffh, g_ffh); cudaGetSymbolAddress((void**)&ffl, g_ffl);
    cudaGetSymbolAddress((void**)&tmp, g_tmp);
    cudaGetSymbolAddress((void**)&r1f, g_r1f);
    cudaGetSymbolAddress((void**)&tmp2, g_tmp2);

    cudaFuncSetAttribute(gemm_bf<0,1,1>, cudaFuncAttributeMaxDynamicSharedMemorySize, GEMM_SMEM);
    cudaFuncSetAttribute(gemm_bf<1,1,0>, cudaFuncAttributeMaxDynamicSharedMemorySize, GEMM_SMEM);
    cudaFuncSetAttribute(gemm_bf<2,0,0>, cudaFuncAttributeMaxDynamicSharedMemorySize, GEMM_SMEM);
    cudaFuncSetAttribute(flash_bf, cudaFuncAttributeMaxDynamicSharedMemorySize, FA_SMEM);

    const dim3 blk(256);

    // ---- conversion passes ----
    cvt_hl<<<NELEM / 4 / 256, blk>>>(x,  xh,  xl,  NELEM / 4);
    cvt_hl<<<WELEM / 4 / 256, blk>>>(Wq, wqh, wql, WELEM / 4);
    cvt_hl<<<WELEM / 4 / 256, blk>>>(Wk, wkh, wkl, WELEM / 4);
    cvt_hl<<<WELEM / 4 / 256, blk>>>(Wv, wvh, wvl, WELEM / 4);
    cvt_hl<<<WELEM / 4 / 256, blk>>>(Wo, woh, wol, WELEM / 4);
    cvt_hl<<<FELEM / 4 / 256, blk>>>(W1, w1h, w1l, FELEM / 4);
    cvt_hl<<<FELEM / 4 / 256, blk>>>(W2, w2h, w2l, FELEM / 4);

    const dim3 gQKV(24, MROWS / 256);            // (24, 16) fused QKV
    const dim3 gD(D_MODEL / 128, MROWS / 256);   // (8, 16)
    const dim3 gF(D_FF / 128, MROWS / 256);      // (32, 16)

    // Fused QKV projection -> bf16 hi/lo
    gemm_bf<0,1,1><<<gQKV, blk, GEMM_SMEM>>>(xh, xl, wqh, wql, wkh, wkl, wvh, wvl,
                                             nullptr, nullptr, qh, ql, kh, kl, vh, vl,
                                             MROWS, D_MODEL, D_MODEL);

    // Flash attention (bf16 in/out)
    flash_bf<<<dim3(SEQ / 128, HEADS, BATCH), dim3(512), FA_SMEM>>>(qh, ql, kh, kl, vh, vl, ah, al);

    // Output projection + residual x -> fp32, then LN1 (fp32 + hi/lo)
    gemm_bf<2,0,0><<<gD, blk, GEMM_SMEM>>>(ah, al, woh, wol, nullptr, nullptr, nullptr, nullptr,
                                           x, tmp, nullptr, nullptr, nullptr, nullptr, nullptr, nullptr,
                                           MROWS, D_MODEL, D_MODEL);
    layernorm_k<true><<<MROWS, blk>>>(tmp, g1, b1, r1f, r1h, r1l);

    // FFN
    gemm_bf<1,1,0><<<gF, blk, GEMM_SMEM>>>(r1h, r1l, w1h, w1l, nullptr, nullptr, nullptr, nullptr,
                                           nullptr, nullptr, ffh, ffl, nullptr, nullptr, nullptr, nullptr,
                                           MROWS, D_FF, D_MODEL);
    gemm_bf<2,0,0><<<gD, blk, GEMM_SMEM>>>(ffh, ffl, w2h, w2l, nullptr, nullptr, nullptr, nullptr,
                                           r1f, tmp2, nullptr, nullptr, nullptr, nullptr, nullptr, nullptr,
                                           MROWS, D_MODEL, D_FF);
    layernorm_k<false><<<MROWS, blk>>>(tmp2, g2, b2, out, nullptr, nullptr);
}

// round 12
// speedup vs baseline: 1.3961x; 1.3961x over previous
#include <cuda_runtime.h>
#include <cuda_bf16.h>
#include <cuda_fp16.h>
#include <mma.h>
#include <math.h>
#include <stdint.h>

using namespace nvcuda;

#define D_MODEL 1024
#define HEADS   16
#define DKH     64
#define D_FF    4096
#define BATCH   2
#define SEQ     2048
#define MROWS   (BATCH * SEQ)   // 4096
#define EPS_LN  1e-6f
#define NELEM   (MROWS * D_MODEL)
#define WELEM   (D_MODEL * D_MODEL)
#define FELEM   (D_FF * D_MODEL)
#define FFELEM  (MROWS * D_FF)

// ---------------- scratch (static device globals; no allocs) ----------------
__device__ __half g_xh[NELEM],  g_xl[NELEM];          // x fp16 hi/lo
__device__ __half g_wqh[WELEM], g_wkh[WELEM];          // weights fp16 hi only
__device__ __half g_wvh[WELEM], g_woh[WELEM];
__device__ __half g_w1h[FELEM], g_w2h[FELEM];
__device__ __nv_bfloat16 g_qh[NELEM], g_ql[NELEM];     // q/k/v bf16 hi/lo (flash in)
__device__ __nv_bfloat16 g_kh[NELEM], g_kl[NELEM];
__device__ __nv_bfloat16 g_vh[NELEM], g_vl[NELEM];
__device__ __half g_ah[NELEM],  g_al[NELEM];           // attn out fp16 hi/lo
__device__ __half g_r1h[NELEM], g_r1l[NELEM];          // LN1 out fp16 hi/lo
__device__ __half g_ffh[FFELEM], g_ffl[FFELEM];        // relu(ff) fp16 hi/lo
__device__ float g_tmp[NELEM];
__device__ float g_r1f[NELEM];
__device__ float g_tmp2[NELEM];

// ================= helpers ===================================================
__device__ __forceinline__ void split2(float a, float b, uint32_t& hi, uint32_t& lo) {
    __nv_bfloat16 ha = __float2bfloat16_rn(a);
    __nv_bfloat16 hb = __float2bfloat16_rn(b);
    float la = a - __bfloat162float(ha);
    float lb = b - __bfloat162float(hb);
    __nv_bfloat162 hv = __halves2bfloat162(ha, hb);
    __nv_bfloat162 lv = __floats2bfloat162_rn(la, lb);
    hi = *reinterpret_cast<uint32_t*>(&hv);
    lo = *reinterpret_cast<uint32_t*>(&lv);
}

__device__ __forceinline__ void split2h(float a, float b, uint32_t& hi, uint32_t& lo) {
    __half ha = __float2half_rn(a);
    __half hb = __float2half_rn(b);
    float la = a - __half2float(ha);
    float lb = b - __half2float(hb);
    __half2 hv = __halves2half2(ha, hb);
    __half2 lv = __floats2half2_rn(la, lb);
    hi = *reinterpret_cast<uint32_t*>(&hv);
    lo = *reinterpret_cast<uint32_t*>(&lv);
}

#define CP16(dst, src) \
    asm volatile("cp.async.cg.shared.global [%0], [%1], 16;" :: \
        "r"((uint32_t)__cvta_generic_to_shared(dst)), "l"(src))
#define CP_COMMIT() asm volatile("cp.async.commit_group;" ::: "memory")
#define CP_WAIT(n)  asm volatile("cp.async.wait_group %0;" :: "n"(n) : "memory")

// ---------------- conversions ------------------------------------------------
__global__ __launch_bounds__(256)
void cvt_h16(const float* __restrict__ src, __half* __restrict__ hi, int n4)
{
    int i = blockIdx.x * 256 + threadIdx.x;
    if (i < n4) {
        float4 v = ((const float4*)src)[i];
        __half2 h01 = __floats2half2_rn(v.x, v.y);
        __half2 h23 = __floats2half2_rn(v.z, v.w);
        ((uint2*)hi)[i] = make_uint2(*(uint32_t*)&h01, *(uint32_t*)&h23);
    }
}

__global__ __launch_bounds__(256)
void cvt_hl16(const float* __restrict__ src, __half* __restrict__ hi,
              __half* __restrict__ lo, int n4)
{
    int i = blockIdx.x * 256 + threadIdx.x;
    if (i < n4) {
        float4 v = ((const float4*)src)[i];
        uint32_t h01, l01, h23, l23;
        split2h(v.x, v.y, h01, l01);
        split2h(v.z, v.w, h23, l23);
        ((uint2*)hi)[i] = make_uint2(h01, h23);
        ((uint2*)lo)[i] = make_uint2(l01, l23);
    }
}

// ================= fp16x2 GEMM: C = A @ B^T (+epilogue) ======================
// A split fp16 hi/lo, B fp16 (rounded). 2 MMA passes.
// block 128x128, 8 warps (4m x 2n), warp tile 32x64, k-chunk 32, 2 stages.
// EPI: 0 none, 1 relu, 2 residual. OUT: 0 fp32, 1 bf16 hi/lo, 2 fp16 hi/lo.
#define GLDT    40
#define GTILE   (128 * GLDT)                 // 5120 halves
#define GSTAGE  (3 * GTILE)                  // Ah, Al, Bh
#define GSTAGES 2
#define GEMM_SMEM 67584                      // max(2*GSTAGE*2=61440, 128*132*4)

__device__ __forceinline__ void gemm_issue(__half* st,
    const __half* Ahg, const __half* Alg, const __half* Bhg,
    int K, int k0, int tid)
{
    __half* sAh = st;
    __half* sAl = st + GTILE;
    __half* sBh = st + 2 * GTILE;
#pragma unroll
    for (int it = 0; it < 2; it++) {
        int ch = tid + it * 256;          // 0..511
        int r = ch >> 2;                  // 0..127
        int c = (ch & 3) * 8;             // 0..24
        CP16(sAh + r * GLDT + c, Ahg + (size_t)r * K + k0 + c);
        CP16(sAl + r * GLDT + c, Alg + (size_t)r * K + k0 + c);
        CP16(sBh + r * GLDT + c, Bhg + (size_t)r * K + k0 + c);
    }
}

template <int EPI, int OUT, int QKV>
__global__ __launch_bounds__(256, 2)
void gemm_fp16(const __half* __restrict__ Ah, const __half* __restrict__ Al,
               const __half* __restrict__ Bh1, const __half* __restrict__ Bh2,
               const __half* __restrict__ Bh3,
               const float* __restrict__ Rf, float* __restrict__ Cf,
               __nv_bfloat16* __restrict__ Ch1, __nv_bfloat16* __restrict__ Cl1,
               __nv_bfloat16* __restrict__ Ch2, __nv_bfloat16* __restrict__ Cl2,
               __nv_bfloat16* __restrict__ Ch3, __nv_bfloat16* __restrict__ Cl3,
               __half* __restrict__ Hh, __half* __restrict__ Hl,
               int M, int N, int K)
{
    extern __shared__ __half sh[];

    const int tid = threadIdx.x;
    const int wid = tid >> 5;
    const int wm = (wid & 3) * 32;
    const int wn = (wid >> 2) * 64;

    const __half* Bh = Bh1;
    __nv_bfloat16* Ch = Ch1;
    __nv_bfloat16* Cl = Cl1;
    int col0;
    if (QKV) {
        const int mat = blockIdx.x >> 3;      // 0,1,2 -> q,k,v
        col0 = (blockIdx.x & 7) * 128;
        if (mat == 1) { Bh = Bh2; Ch = Ch2; Cl = Cl2; }
        else if (mat == 2) { Bh = Bh3; Ch = Ch3; Cl = Cl3; }
    } else {
        col0 = blockIdx.x * 128;
    }
    const int row0 = blockIdx.y * 128;
    const __half* Ahg = Ah + (size_t)row0 * K;
    const __half* Alg = Al + (size_t)row0 * K;
    const __half* Bhg = Bh + (size_t)col0 * K;

    wmma::fragment<wmma::accumulator, 16, 16, 16, float> acc[2][4];
#pragma unroll
    for (int i = 0; i < 2; i++)
#pragma unroll
        for (int j = 0; j < 4; j++) wmma::fill_fragment(acc[i][j], 0.f);

    const int T = K / 32;
    gemm_issue(sh, Ahg, Alg, Bhg, K, 0, tid);
    CP_COMMIT();

    for (int t = 0; t < T; t++) {
        CP_WAIT(0);
        __syncthreads();
        if (t + 1 < T) {
            gemm_issue(sh + ((t + 1) & 1) * GSTAGE, Ahg, Alg, Bhg,
                       K, (t + 1) * 32, tid);
            CP_COMMIT();
        }
        __half* Ahs = sh + (t & 1) * GSTAGE;
        __half* Als = Ahs + GTILE;
        __half* Bhs = Ahs + 2 * GTILE;
#pragma unroll
        for (int ks = 0; ks < 32; ks += 16) {
            wmma::fragment<wmma::matrix_a, 16, 16, 16, __half, wmma::row_major> a_hi[2], a_lo[2];
#pragma unroll
            for (int i = 0; i < 2; i++) {
                wmma::load_matrix_sync(a_hi[i], Ahs + (wm + i * 16) * GLDT + ks, GLDT);
                wmma::load_matrix_sync(a_lo[i], Als + (wm + i * 16) * GLDT + ks, GLDT);
            }
#pragma unroll
            for (int j = 0; j < 4; j++) {
                wmma::fragment<wmma::matrix_b, 16, 16, 16, __half, wmma::col_major> b_hi;
                wmma::load_matrix_sync(b_hi, Bhs + (wn + j * 16) * GLDT + ks, GLDT);
#pragma unroll
                for (int i = 0; i < 2; i++) {
                    wmma::mma_sync(acc[i][j], a_hi[i], b_hi, acc[i][j]);
                    wmma::mma_sync(acc[i][j], a_lo[i], b_hi, acc[i][j]);
                }
            }
        }
        __syncthreads();
    }

    if (OUT == 0) {
#pragma unroll
        for (int i = 0; i < 2; i++) {
#pragma unroll
            for (int j = 0; j < 4; j++) {
                const int row = row0 + wm + i * 16;
                const int col = col0 + wn + j * 16;
                if (EPI == 2) {
                    wmma::fragment<wmma::accumulator, 16, 16, 16, float> rf;
                    wmma::load_matrix_sync(rf, Rf + (size_t)row * N + col, N, wmma::mem_row_major);
#pragma unroll
                    for (int e = 0; e < rf.num_elements; e++) acc[i][j].x[e] += rf.x[e];
                }
                if (EPI == 1) {
#pragma unroll
                    for (int e = 0; e < acc[i][j].num_elements; e++)
                        acc[i][j].x[e] = fmaxf(acc[i][j].x[e], 0.f);
                }
                wmma::store_matrix_sync(Cf + (size_t)row * N + col, acc[i][j], N, wmma::mem_row_major);
            }
        }
    } else {
        // stage fp32 tile in smem, then split-store (bf16 or fp16 hi/lo)
        float* stg = (float*)sh;              // 128 x 132 fp32 = 67584 B
        __syncthreads();
#pragma unroll
        for (int i = 0; i < 2; i++) {
#pragma unroll
            for (int j = 0; j < 4; j++) {
                if (EPI == 1) {
#pragma unroll
                    for (int e = 0; e < acc[i][j].num_elements; e++)
                        acc[i][j].x[e] = fmaxf(acc[i][j].x[e], 0.f);
                }
                wmma::store_matrix_sync(stg + (wm + i * 16) * 132 + wn + j * 16,
                                        acc[i][j], 132, wmma::mem_row_major);
            }
        }
        __syncthreads();
        const int r = tid >> 1;
        const int cb = (tid & 1) * 64;
#pragma unroll
        for (int j = 0; j < 64; j += 4) {
            float4 v = *(const float4*)(stg + r * 132 + cb + j);
            uint32_t h01, l01, h23, l23;
            const size_t off = (size_t)(row0 + r) * N + col0 + cb + j;
            if (OUT == 1) {
                split2(v.x, v.y, h01, l01);
                split2(v.z, v.w, h23, l23);
                *(uint2*)(Ch + off) = make_uint2(h01, h23);
                *(uint2*)(Cl + off) = make_uint2(l01, l23);
            } else {
                split2h(v.x, v.y, h01, l01);
                split2h(v.z, v.w, h23, l23);
                *(uint2*)(Hh + off) = make_uint2(h01, h23);
                *(uint2*)(Hl + off) = make_uint2(l01, l23);
            }
        }
    }
}

// ================= WMMA flash attention (bf16x3 in, fp16 out, fp32 softmax) ==
#define LDH 72
#define LDF 68
#define FO_QH 0
#define FO_QL (FO_QH + 128 * LDH * 2)
#define FO_KH (FO_QL + 128 * LDH * 2)
#define FO_KL (FO_KH + 64 * LDH * 2)
#define FO_VH (FO_KL + 64 * LDH * 2)
#define FO_VL (FO_VH + 64 * LDH * 2)
#define FO_PH (FO_VL + 64 * LDH * 2)
#define FO_PL (FO_PH + 128 * LDH * 2)
#define FO_SF (FO_PL + 128 * LDH * 2)
#define FO_MR (FO_SF + 128 * LDF * 4)
#define FO_LR (FO_MR + 512)
#define FO_CR (FO_LR + 512)
#define FA_SMEM (FO_CR + 512)             // 146944 B

__global__ __launch_bounds__(512)
void flash_bf(const __nv_bfloat16* __restrict__ Qh_g, const __nv_bfloat16* __restrict__ Ql_g,
              const __nv_bfloat16* __restrict__ Kh_g, const __nv_bfloat16* __restrict__ Kl_g,
              const __nv_bfloat16* __restrict__ Vh_g, const __nv_bfloat16* __restrict__ Vl_g,
              __half* __restrict__ Oh_g, __half* __restrict__ Ol_g)
{
    extern __shared__ char fsm[];
    __nv_bfloat16* Qh = (__nv_bfloat16*)(fsm + FO_QH);
    __nv_bfloat16* Ql = (__nv_bfloat16*)(fsm + FO_QL);
    __nv_bfloat16* Kh = (__nv_bfloat16*)(fsm + FO_KH);
    __nv_bfloat16* Kl = (__nv_bfloat16*)(fsm + FO_KL);
    __nv_bfloat16* Vh = (__nv_bfloat16*)(fsm + FO_VH);
    __nv_bfloat16* Vl = (__nv_bfloat16*)(fsm + FO_VL);
    __nv_bfloat16* Ph = (__nv_bfloat16*)(fsm + FO_PH);
    __nv_bfloat16* Pl = (__nv_bfloat16*)(fsm + FO_PL);
    float* Sf   = (float*)(fsm + FO_SF);
    float* mrow = (float*)(fsm + FO_MR);
    float* lrow = (float*)(fsm + FO_LR);
    float* crow = (float*)(fsm + FO_CR);

    const int qb = gridDim.x - 1 - blockIdx.x;   // heavy q-blocks first
    const int h = blockIdx.y, bb = blockIdx.z;
    const int tid = threadIdx.x;
    const int wid = tid >> 5;
    const int wm = (wid & 3) * 32;
    const int wn = (wid >> 2) * 16;
    const int q0 = qb * 128;
    const size_t base = (size_t)bb * SEQ * D_MODEL + (size_t)h * DKH;

    const int r  = tid >> 2;
    const int c0 = (tid & 3) * 16;

    {
        const size_t g = base + (size_t)(q0 + r) * D_MODEL + c0;
        *(uint4*)(Qh + r * LDH + c0)     = *(const uint4*)(Qh_g + g);
        *(uint4*)(Qh + r * LDH + c0 + 8) = *(const uint4*)(Qh_g + g + 8);
        *(uint4*)(Ql + r * LDH + c0)     = *(const uint4*)(Ql_g + g);
        *(uint4*)(Ql + r * LDH + c0 + 8) = *(const uint4*)(Ql_g + g + 8);
    }
    if (tid < 128) { mrow[tid] = -INFINITY; lrow[tid] = 0.f; }

    float orow[16];
#pragma unroll
    for (int j = 0; j < 16; j++) orow[j] = 0.f;
    __syncthreads();

    const int kmax = 2 * qb + 1;
    for (int kb = 0; kb <= kmax; kb++) {
        const int k0 = kb * 64;

        {
            const int kr = tid >> 3;
            const int kc = (tid & 7) * 8;
            const size_t g = base + (size_t)(k0 + kr) * D_MODEL + kc;
            *(uint4*)(Kh + kr * LDH + kc) = *(const uint4*)(Kh_g + g);
            *(uint4*)(Kl + kr * LDH + kc) = *(const uint4*)(Kl_g + g);
            *(uint4*)(Vh + kr * LDH + kc) = *(const uint4*)(Vh_g + g);
            *(uint4*)(Vl + kr * LDH + kc) = *(const uint4*)(Vl_g + g);
        }
        __syncthreads();

        {
            wmma::fragment<wmma::accumulator, 16, 16, 16, float> accS[2];
#pragma unroll
            for (int i = 0; i < 2; i++) wmma::fill_fragment(accS[i], 0.f);
#pragma unroll
            for (int ks = 0; ks < 64; ks += 16) {
                wmma::fragment<wmma::matrix_a, 16, 16, 16, __nv_bfloat16, wmma::row_major> ah[2], al[2];
                wmma::fragment<wmma::matrix_b, 16, 16, 16, __nv_bfloat16, wmma::col_major> bh, bl;
#pragma unroll
                for (int i = 0; i < 2; i++) {
                    wmma::load_matrix_sync(ah[i], Qh + (wm + i * 16) * LDH + ks, LDH);
                    wmma::load_matrix_sync(al[i], Ql + (wm + i * 16) * LDH + ks, LDH);
                }
                wmma::load_matrix_sync(bh, Kh + wn * LDH + ks, LDH);
                wmma::load_matrix_sync(bl, Kl + wn * LDH + ks, LDH);
#pragma unroll
                for (int i = 0; i < 2; i++) {
                    wmma::mma_sync(accS[i], ah[i], bh, accS[i]);
                    wmma::mma_sync(accS[i], ah[i], bl, accS[i]);
                    wmma::mma_sync(accS[i], al[i], bh, accS[i]);
                }
            }
#pragma unroll
            for (int i = 0; i < 2; i++)
                wmma::store_matrix_sync(Sf + (wm + i * 16) * LDF + wn, accS[i], LDF, wmma::mem_row_major);
        }
        __syncthreads();

        {
            const bool needmask = (k0 + 63 > q0);
            const int qrow = q0 + r;
            float sv[16];
            const float* srow = Sf + r * LDF + c0;
            float mx = -INFINITY;
#pragma unroll
            for (int j = 0; j < 16; j++) {
                float v = srow[j] * 0.125f;
                if (needmask && (k0 + c0 + j) > qrow) v = -INFINITY;
                sv[j] = v;
                mx = fmaxf(mx, v);
            }
            mx = fmaxf(mx, __shfl_xor_sync(0xFFFFFFFFu, mx, 1));
            mx = fmaxf(mx, __shfl_xor_sync(0xFFFFFFFFu, mx, 2));
            const float mold = mrow[r];
            const float mnew = fmaxf(mold, mx);
            float lsum = 0.f;
#pragma unroll
            for (int j = 0; j < 16; j++) {
                float p = __expf(sv[j] - mnew);
                sv[j] = p;
                lsum += p;
            }
            lsum += __shfl_xor_sync(0xFFFFFFFFu, lsum, 1);
            lsum += __shfl_xor_sync(0xFFFFFFFFu, lsum, 2);
#pragma unroll
            for (int j = 0; j < 16; j += 2) {
                uint32_t hv, lv;
                split2(sv[j], sv[j + 1], hv, lv);
                *(uint32_t*)(Ph + r * LDH + c0 + j) = hv;
                *(uint32_t*)(Pl + r * LDH + c0 + j) = lv;
            }
            if ((tid & 3) == 0) {
                const float corr = __expf(mold - mnew);
                mrow[r] = mnew;
                lrow[r] = lrow[r] * corr + lsum;
                crow[r] = corr;
            }
        }
        __syncthreads();

        {
            wmma::fragment<wmma::accumulator, 16, 16, 16, float> accO[2];
#pragma unroll
            for (int i = 0; i < 2; i++) wmma::fill_fragment(accO[i], 0.f);
#pragma unroll
            for (int ks = 0; ks < 64; ks += 16) {
                wmma::fragment<wmma::matrix_a, 16, 16, 16, __nv_bfloat16, wmma::row_major> ah[2], al[2];
                wmma::fragment<wmma::matrix_b, 16, 16, 16, __nv_bfloat16, wmma::row_major> bh, bl;
#pragma unroll
                for (int i = 0; i < 2; i++) {
                    wmma::load_matrix_sync(ah[i], Ph + (wm + i * 16) * LDH + ks, LDH);
                    wmma::load_matrix_sync(al[i], Pl + (wm + i * 16) * LDH + ks, LDH);
                }
                wmma::load_matrix_sync(bh, Vh + ks * LDH + wn, LDH);
                wmma::load_matrix_sync(bl, Vl + ks * LDH + wn, LDH);
#pragma unroll
                for (int i = 0; i < 2; i++) {
                    wmma::mma_sync(accO[i], ah[i], bh, accO[i]);
                    wmma::mma_sync(accO[i], ah[i], bl, accO[i]);
                    wmma::mma_sync(accO[i], al[i], bh, accO[i]);
                }
            }
#pragma unroll
            for (int i = 0; i < 2; i++)
                wmma::store_matrix_sync(Sf + (wm + i * 16) * LDF + wn, accO[i], LDF, wmma::mem_row_major);
        }
        __syncthreads();

        {
            const float corr = crow[r];
            const float* prow = Sf + r * LDF + c0;
#pragma unroll
            for (int j = 0; j < 16; j++) orow[j] = orow[j] * corr + prow[j];
        }
        __syncthreads();
    }

    {
        const float inv = 1.f / lrow[r];
        const size_t g = base + (size_t)(q0 + r) * D_MODEL + c0;
#pragma unroll
        for (int j = 0; j < 16; j += 2) {
            uint32_t hv, lv;
            split2h(orow[j] * inv, orow[j + 1] * inv, hv, lv);
            *(uint32_t*)(Oh_g + g + j) = hv;
            *(uint32_t*)(Ol_g + g + j) = lv;
        }
    }
}

// ---------------- LayerNorm (ddof=1), optional fp16 hi/lo output -------------
template <bool HL>
__global__ __launch_bounds__(256)
void layernorm_k(const float* __restrict__ in, const float* __restrict__ gamma,
                 const float* __restrict__ beta, float* __restrict__ out,
                 __half* __restrict__ oh, __half* __restrict__ ol)
{
    const int row = blockIdx.x;
    const int tid = threadIdx.x;
    const float4 v = ((const float4*)(in + (size_t)row * D_MODEL))[tid];
    float s  = v.x + v.y + v.z + v.w;
    float ss = v.x * v.x + v.y * v.y + v.z * v.z + v.w * v.w;

    __shared__ float rs[8], rss[8];
#pragma unroll
    for (int o = 16; o > 0; o >>= 1) {
        s  += __shfl_down_sync(0xFFFFFFFFu, s, o);
        ss += __shfl_down_sync(0xFFFFFFFFu, ss, o);
    }
    if ((tid & 31) == 0) { rs[tid >> 5] = s; rss[tid >> 5] = ss; }
    __syncthreads();
    float S = 0.f, SS = 0.f;
#pragma unroll
    for (int i = 0; i < 8; i++) { S += rs[i]; SS += rss[i]; }

    const float mean = S * (1.f / (float)D_MODEL);
    const float var  = (SS - (float)D_MODEL * mean * mean) * (1.f / (float)(D_MODEL - 1));
    const float inv  = rsqrtf(var + EPS_LN);

    const float4 g = ((const float4*)gamma)[tid];
    const float4 b = ((const float4*)beta)[tid];
    float4 o;
    o.x = g.x * (v.x - mean) * inv + b.x;
    o.y = g.y * (v.y - mean) * inv + b.y;
    o.z = g.z * (v.z - mean) * inv + b.z;
    o.w = g.w * (v.w - mean) * inv + b.w;
    ((float4*)(out + (size_t)row * D_MODEL))[tid] = o;
    if (HL) {
        uint32_t h01, l01, h23, l23;
        split2h(o.x, o.y, h01, l01);
        split2h(o.z, o.w, h23, l23);
        ((uint2*)(oh + (size_t)row * D_MODEL))[tid] = make_uint2(h01, h23);
        ((uint2*)(ol + (size_t)row * D_MODEL))[tid] = make_uint2(l01, l23);
    }
}

// ---------------- host launcher ---------------------------------------------
extern "C" void kernel_launch(void* const* d_in, const int* in_sizes, int n_in,
                              void* d_out, int out_size)
{
    (void)in_sizes; (void)n_in; (void)out_size;
    const float* x  = (const float*)d_in[0];
    const float* Wq = (const float*)d_in[2];
    const float* Wk = (const float*)d_in[3];
    const float* Wv = (const float*)d_in[4];
    const float* Wo = (const float*)d_in[5];
    const float* W1 = (const float*)d_in[6];
    const float* W2 = (const float*)d_in[7];
    const float* g1 = (const float*)d_in[8];
    const float* b1 = (const float*)d_in[9];
    const float* g2 = (const float*)d_in[10];
    const float* b2 = (const float*)d_in[11];
    float* out = (float*)d_out;

    __half *xh, *xl, *wqh, *wkh, *wvh, *woh, *w1h, *w2h;
    __half *ah, *al, *r1h, *r1l, *ffh, *ffl;
    __nv_bfloat16 *qh, *ql, *kh, *kl, *vh, *vl;
    float *tmp, *r1f, *tmp2;
    cudaGetSymbolAddress((void**)&xh, g_xh);   cudaGetSymbolAddress((void**)&xl, g_xl);
    cudaGetSymbolAddress((void**)&wqh, g_wqh); cudaGetSymbolAddress((void**)&wkh, g_wkh);
    cudaGetSymbolAddress((void**)&wvh, g_wvh); cudaGetSymbolAddress((void**)&woh, g_woh);
    cudaGetSymbolAddress((void**)&w1h, g_w1h); cudaGetSymbolAddress((void**)&w2h, g_w2h);
    cudaGetSymbolAddress((void**)&qh, g_qh);   cudaGetSymbolAddress((void**)&ql, g_ql);
    cudaGetSymbolAddress((void**)&kh, g_kh);   cudaGetSymbolAddress((void**)&kl, g_kl);
    cudaGetSymbolAddress((void**)&vh, g_vh);   cudaGetSymbolAddress((void**)&vl, g_vl);
    cudaGetSymbolAddress((void**)&ah, g_ah);   cudaGetSymbolAddress((void**)&al, g_al);
    cudaGetSymbolAddress((void**)&r1h, g_r1h); cudaGetSymbolAddress((void**)&r1l, g_r1l);
    cudaGetSymbolAddress((void**)&ffh, g_ffh); cudaGetSymbolAddress((void**)&ffl, g_ffl);
    cudaGetSymbolAddress((void**)&tmp, g_tmp);
    cudaGetSymbolAddress((void**)&r1f, g_r1f);
    cudaGetSymbolAddress((void**)&tmp2, g_tmp2);

    cudaFuncSetAttribute(gemm_fp16<0,1,1>, cudaFuncAttributeMaxDynamicSharedMemorySize, GEMM_SMEM);
    cudaFuncSetAttribute(gemm_fp16<1,2,0>, cudaFuncAttributeMaxDynamicSharedMemorySize, GEMM_SMEM);
    cudaFuncSetAttribute(gemm_fp16<2,0,0>, cudaFuncAttributeMaxDynamicSharedMemorySize, GEMM_SMEM);
    cudaFuncSetAttribute(flash_bf, cudaFuncAttributeMaxDynamicSharedMemorySize, FA_SMEM);

    const dim3 blk(256);

    // ---- conversion passes ----
    cvt_hl16<<<NELEM / 4 / 256, blk>>>(x, xh, xl, NELEM / 4);
    cvt_h16<<<WELEM / 4 / 256, blk>>>(Wq, wqh, WELEM / 4);
    cvt_h16<<<WELEM / 4 / 256, blk>>>(Wk, wkh, WELEM / 4);
    cvt_h16<<<WELEM / 4 / 256, blk>>>(Wv, wvh, WELEM / 4);
    cvt_h16<<<WELEM / 4 / 256, blk>>>(Wo, woh, WELEM / 4);
    cvt_h16<<<FELEM / 4 / 256, blk>>>(W1, w1h, FELEM / 4);
    cvt_h16<<<FELEM / 4 / 256, blk>>>(W2, w2h, FELEM / 4);

    const dim3 gQKV(24, MROWS / 128);            // fused QKV
    const dim3 gD(D_MODEL / 128, MROWS / 128);   // (8, 32)
    const dim3 gF(D_FF / 128, MROWS / 128);      // (32, 32)

    // Fused QKV projection -> bf16 hi/lo (flash inputs)
    gemm_fp16<0,1,1><<<gQKV, blk, GEMM_SMEM>>>(xh, xl, wqh, wkh, wvh,
                                               nullptr, nullptr,
                                               qh, ql, kh, kl, vh, vl,
                                               nullptr, nullptr,
                                               MROWS, D_MODEL, D_MODEL);

    // Flash attention (bf16 in, fp16 hi/lo out)
    flash_bf<<<dim3(SEQ / 128, HEADS, BATCH), dim3(512), FA_SMEM>>>(qh, ql, kh, kl, vh, vl, ah, al);

    // Output projection + residual x -> fp32, then LN1 (fp32 + fp16 hi/lo)
    gemm_fp16<2,0,0><<<gD, blk, GEMM_SMEM>>>(ah, al, woh, nullptr, nullptr,
                                             x, tmp,
                                             nullptr, nullptr, nullptr, nullptr, nullptr, nullptr,
                                             nullptr, nullptr,
                                             MROWS, D_MODEL, D_MODEL);
    layernorm_k<true><<<MROWS, blk>>>(tmp, g1, b1, r1f, r1h, r1l);

    // FFN
    gemm_fp16<1,2,0><<<gF, blk, GEMM_SMEM>>>(r1h, r1l, w1h, nullptr, nullptr,
                                             nullptr, nullptr,
                                             nullptr, nullptr, nullptr, nullptr, nullptr, nullptr,
                                             ffh, ffl,
                                             MROWS, D_FF, D_MODEL);
    gemm_fp16<2,0,0><<<gD, blk, GEMM_SMEM>>>(ffh, ffl, w2h, nullptr, nullptr,
                                             r1f, tmp2,
                                             nullptr, nullptr, nullptr, nullptr, nullptr, nullptr,
                                             nullptr, nullptr,
                                             MROWS, D_MODEL, D_FF);
    layernorm_k<false><<<MROWS, blk>>>(tmp2, g2, b2, out, nullptr, nullptr);
}

// round 14
// speedup vs baseline: 1.5643x; 1.1205x over previous
#include <cuda_runtime.h>
#include <cuda_fp16.h>
#include <mma.h>
#include <math.h>
#include <stdint.h>

using namespace nvcuda;

#define D_MODEL 1024
#define HEADS   16
#define DKH     64
#define D_FF    4096
#define BATCH   2
#define SEQ     2048
#define MROWS   (BATCH * SEQ)   // 4096
#define EPS_LN  1e-6f
#define NELEM   (MROWS * D_MODEL)
#define WELEM   (D_MODEL * D_MODEL)
#define FELEM   (D_FF * D_MODEL)
#define FFELEM  (MROWS * D_FF)

// ---------------- scratch (static device globals; no allocs) ----------------
__device__ __half g_xh[NELEM],  g_xl[NELEM];          // x fp16 hi/lo
__device__ __half g_wqh[WELEM], g_wkh[WELEM];          // weights fp16 hi only
__device__ __half g_wvh[WELEM], g_woh[WELEM];
__device__ __half g_w1h[FELEM], g_w2h[FELEM];
__device__ __half g_qh[NELEM], g_ql[NELEM];            // q fp16 hi/lo
__device__ __half g_kh[NELEM], g_kl[NELEM];            // k fp16 hi (+lo unused by flash)
__device__ __half g_vh[NELEM], g_vl[NELEM];            // v fp16 hi (+lo unused by flash)
__device__ __half g_ah[NELEM],  g_al[NELEM];           // attn out fp16 hi/lo
__device__ __half g_r1h[NELEM], g_r1l[NELEM];          // LN1 out fp16 hi/lo
__device__ __half g_ffh[FFELEM], g_ffl[FFELEM];        // relu(ff) fp16 hi/lo
__device__ float g_tmp[NELEM];
__device__ float g_r1f[NELEM];
__device__ float g_tmp2[NELEM];

// ================= helpers ===================================================
__device__ __forceinline__ void split2h(float a, float b, uint32_t& hi, uint32_t& lo) {
    __half ha = __float2half_rn(a);
    __half hb = __float2half_rn(b);
    float la = a - __half2float(ha);
    float lb = b - __half2float(hb);
    __half2 hv = __halves2half2(ha, hb);
    __half2 lv = __floats2half2_rn(la, lb);
    hi = *reinterpret_cast<uint32_t*>(&hv);
    lo = *reinterpret_cast<uint32_t*>(&lv);
}

#define CP16(dst, src) \
    asm volatile("cp.async.cg.shared.global [%0], [%1], 16;" :: \
        "r"((uint32_t)__cvta_generic_to_shared(dst)), "l"(src))
#define CP_COMMIT() asm volatile("cp.async.commit_group;" ::: "memory")
#define CP_WAIT(n)  asm volatile("cp.async.wait_group %0;" :: "n"(n) : "memory")

// ---------------- conversions ------------------------------------------------
__global__ __launch_bounds__(256)
void cvt_h16(const float* __restrict__ src, __half* __restrict__ hi, int n4)
{
    int i = blockIdx.x * 256 + threadIdx.x;
    if (i < n4) {
        float4 v = ((const float4*)src)[i];
        __half2 h01 = __floats2half2_rn(v.x, v.y);
        __half2 h23 = __floats2half2_rn(v.z, v.w);
        ((uint2*)hi)[i] = make_uint2(*(uint32_t*)&h01, *(uint32_t*)&h23);
    }
}

__global__ __launch_bounds__(256)
void cvt_hl16(const float* __restrict__ src, __half* __restrict__ hi,
              __half* __restrict__ lo, int n4)
{
    int i = blockIdx.x * 256 + threadIdx.x;
    if (i < n4) {
        float4 v = ((const float4*)src)[i];
        uint32_t h01, l01, h23, l23;
        split2h(v.x, v.y, h01, l01);
        split2h(v.z, v.w, h23, l23);
        ((uint2*)hi)[i] = make_uint2(h01, h23);
        ((uint2*)lo)[i] = make_uint2(l01, l23);
    }
}

// ================= fp16x2 GEMM: C = A @ B^T (+epilogue) ======================
// A split fp16 hi/lo, B fp16 (rounded). 2 MMA passes.
// block 128x128, 8 warps (4m x 2n), warp tile 32x64, k-chunk 32, 2 stages.
// EPI: 0 none, 1 relu, 2 residual. OUT: 0 fp32, 2 fp16 hi/lo.
#define GLDT    40
#define GTILE   (128 * GLDT)                 // 5120 halves
#define GSTAGE  (3 * GTILE)                  // Ah, Al, Bh
#define GSTAGES 2
#define GEMM_SMEM 67584                      // max(2*GSTAGE*2=61440, 128*132*4)

__device__ __forceinline__ void gemm_issue(__half* st,
    const __half* Ahg, const __half* Alg, const __half* Bhg,
    int K, int k0, int tid)
{
    __half* sAh = st;
    __half* sAl = st + GTILE;
    __half* sBh = st + 2 * GTILE;
#pragma unroll
    for (int it = 0; it < 2; it++) {
        int ch = tid + it * 256;          // 0..511
        int r = ch >> 2;                  // 0..127
        int c = (ch & 3) * 8;             // 0..24
        CP16(sAh + r * GLDT + c, Ahg + (size_t)r * K + k0 + c);
        CP16(sAl + r * GLDT + c, Alg + (size_t)r * K + k0 + c);
        CP16(sBh + r * GLDT + c, Bhg + (size_t)r * K + k0 + c);
    }
}

template <int EPI, int OUT, int QKV>
__global__ __launch_bounds__(256, 2)
void gemm_fp16(const __half* __restrict__ Ah, const __half* __restrict__ Al,
               const __half* __restrict__ Bh1, const __half* __restrict__ Bh2,
               const __half* __restrict__ Bh3,
               const float* __restrict__ Rf, float* __restrict__ Cf,
               __half* __restrict__ Hh1, __half* __restrict__ Hl1,
               __half* __restrict__ Hh2, __half* __restrict__ Hl2,
               __half* __restrict__ Hh3, __half* __restrict__ Hl3,
               int M, int N, int K)
{
    extern __shared__ __half sh[];

    const int tid = threadIdx.x;
    const int wid = tid >> 5;
    const int wm = (wid & 3) * 32;
    const int wn = (wid >> 2) * 64;

    const __half* Bh = Bh1;
    __half* Hh = Hh1;
    __half* Hl = Hl1;
    int col0;
    if (QKV) {
        const int mat = blockIdx.x >> 3;      // 0,1,2 -> q,k,v
        col0 = (blockIdx.x & 7) * 128;
        if (mat == 1) { Bh = Bh2; Hh = Hh2; Hl = Hl2; }
        else if (mat == 2) { Bh = Bh3; Hh = Hh3; Hl = Hl3; }
    } else {
        col0 = blockIdx.x * 128;
    }
    const int row0 = blockIdx.y * 128;
    const __half* Ahg = Ah + (size_t)row0 * K;
    const __half* Alg = Al + (size_t)row0 * K;
    const __half* Bhg = Bh + (size_t)col0 * K;

    wmma::fragment<wmma::accumulator, 16, 16, 16, float> acc[2][4];
#pragma unroll
    for (int i = 0; i < 2; i++)
#pragma unroll
        for (int j = 0; j < 4; j++) wmma::fill_fragment(acc[i][j], 0.f);

    const int T = K / 32;
    gemm_issue(sh, Ahg, Alg, Bhg, K, 0, tid);
    CP_COMMIT();

    for (int t = 0; t < T; t++) {
        CP_WAIT(0);
        __syncthreads();
        if (t + 1 < T) {
            gemm_issue(sh + ((t + 1) & 1) * GSTAGE, Ahg, Alg, Bhg,
                       K, (t + 1) * 32, tid);
            CP_COMMIT();
        }
        __half* Ahs = sh + (t & 1) * GSTAGE;
        __half* Als = Ahs + GTILE;
        __half* Bhs = Ahs + 2 * GTILE;
#pragma unroll
        for (int ks = 0; ks < 32; ks += 16) {
            wmma::fragment<wmma::matrix_a, 16, 16, 16, __half, wmma::row_major> a_hi[2], a_lo[2];
#pragma unroll
            for (int i = 0; i < 2; i++) {
                wmma::load_matrix_sync(a_hi[i], Ahs + (wm + i * 16) * GLDT + ks, GLDT);
                wmma::load_matrix_sync(a_lo[i], Als + (wm + i * 16) * GLDT + ks, GLDT);
            }
#pragma unroll
            for (int j = 0; j < 4; j++) {
                wmma::fragment<wmma::matrix_b, 16, 16, 16, __half, wmma::col_major> b_hi;
                wmma::load_matrix_sync(b_hi, Bhs + (wn + j * 16) * GLDT + ks, GLDT);
#pragma unroll
                for (int i = 0; i < 2; i++) {
                    wmma::mma_sync(acc[i][j], a_hi[i], b_hi, acc[i][j]);
                    wmma::mma_sync(acc[i][j], a_lo[i], b_hi, acc[i][j]);
                }
            }
        }
        __syncthreads();
    }

    if (OUT == 0) {
#pragma unroll
        for (int i = 0; i < 2; i++) {
#pragma unroll
            for (int j = 0; j < 4; j++) {
                const int row = row0 + wm + i * 16;
                const int col = col0 + wn + j * 16;
                if (EPI == 2) {
                    wmma::fragment<wmma::accumulator, 16, 16, 16, float> rf;
                    wmma::load_matrix_sync(rf, Rf + (size_t)row * N + col, N, wmma::mem_row_major);
#pragma unroll
                    for (int e = 0; e < rf.num_elements; e++) acc[i][j].x[e] += rf.x[e];
                }
                if (EPI == 1) {
#pragma unroll
                    for (int e = 0; e < acc[i][j].num_elements; e++)
                        acc[i][j].x[e] = fmaxf(acc[i][j].x[e], 0.f);
                }
                wmma::store_matrix_sync(Cf + (size_t)row * N + col, acc[i][j], N, wmma::mem_row_major);
            }
        }
    } else {
        // stage fp32 tile in smem, then fp16 hi/lo split-store
        float* stg = (float*)sh;              // 128 x 132 fp32 = 67584 B
        __syncthreads();
#pragma unroll
        for (int i = 0; i < 2; i++) {
#pragma unroll
            for (int j = 0; j < 4; j++) {
                if (EPI == 1) {
#pragma unroll
                    for (int e = 0; e < acc[i][j].num_elements; e++)
                        acc[i][j].x[e] = fmaxf(acc[i][j].x[e], 0.f);
                }
                wmma::store_matrix_sync(stg + (wm + i * 16) * 132 + wn + j * 16,
                                        acc[i][j], 132, wmma::mem_row_major);
            }
        }
        __syncthreads();
        const int r = tid >> 1;
        const int cb = (tid & 1) * 64;
#pragma unroll
        for (int j = 0; j < 64; j += 4) {
            float4 v = *(const float4*)(stg + r * 132 + cb + j);
            uint32_t h01, l01, h23, l23;
            split2h(v.x, v.y, h01, l01);
            split2h(v.z, v.w, h23, l23);
            const size_t off = (size_t)(row0 + r) * N + col0 + cb + j;
            *(uint2*)(Hh + off) = make_uint2(h01, h23);
            *(uint2*)(Hl + off) = make_uint2(l01, l23);
        }
    }
}

// ================= fp16x2 flash attention (fp32 softmax) =====================
// Q fp16 hi/lo, K fp16 (rounded), V fp16 (rounded), P fp16 hi/lo.
// S = Qh*Kh + Ql*Kh (2 passes); PV = Ph*Vh + Pl*Vh (2 passes).
// grid: (SEQ/128, HEADS, BATCH), 512 threads = 16 warps (4m x 4n).
#define LDH 72
#define LDF 68
#define FO_QH 0
#define FO_QL (FO_QH + 128 * LDH * 2)     // 18432
#define FO_KH (FO_QL + 128 * LDH * 2)     // 36864
#define FO_VH (FO_KH + 64 * LDH * 2)      // 46080
#define FO_PH (FO_VH + 64 * LDH * 2)      // 55296
#define FO_PL (FO_PH + 128 * LDH * 2)     // 73728
#define FO_SF (FO_PL + 128 * LDH * 2)     // 92160
#define FO_MR (FO_SF + 128 * LDF * 4)     // 126976
#define FO_LR (FO_MR + 512)
#define FO_CR (FO_LR + 512)
#define FA_SMEM (FO_CR + 512)             // 128512 B

__global__ __launch_bounds__(512)
void flash_fp16(const __half* __restrict__ Qh_g, const __half* __restrict__ Ql_g,
                const __half* __restrict__ Kh_g, const __half* __restrict__ Vh_g,
                __half* __restrict__ Oh_g, __half* __restrict__ Ol_g)
{
    extern __shared__ char fsm[];
    __half* Qh = (__half*)(fsm + FO_QH);
    __half* Ql = (__half*)(fsm + FO_QL);
    __half* Kh = (__half*)(fsm + FO_KH);
    __half* Vh = (__half*)(fsm + FO_VH);
    __half* Ph = (__half*)(fsm + FO_PH);
    __half* Pl = (__half*)(fsm + FO_PL);
    float* Sf   = (float*)(fsm + FO_SF);
    float* mrow = (float*)(fsm + FO_MR);
    float* lrow = (float*)(fsm + FO_LR);
    float* crow = (float*)(fsm + FO_CR);

    const int qb = gridDim.x - 1 - blockIdx.x;   // heavy q-blocks first
    const int h = blockIdx.y, bb = blockIdx.z;
    const int tid = threadIdx.x;
    const int wid = tid >> 5;
    const int wm = (wid & 3) * 32;
    const int wn = (wid >> 2) * 16;
    const int q0 = qb * 128;
    const size_t base = (size_t)bb * SEQ * D_MODEL + (size_t)h * DKH;

    const int r  = tid >> 2;
    const int c0 = (tid & 3) * 16;

    {
        const size_t g = base + (size_t)(q0 + r) * D_MODEL + c0;
        *(uint4*)(Qh + r * LDH + c0)     = *(const uint4*)(Qh_g + g);
        *(uint4*)(Qh + r * LDH + c0 + 8) = *(const uint4*)(Qh_g + g + 8);
        *(uint4*)(Ql + r * LDH + c0)     = *(const uint4*)(Ql_g + g);
        *(uint4*)(Ql + r * LDH + c0 + 8) = *(const uint4*)(Ql_g + g + 8);
    }
    if (tid < 128) { mrow[tid] = -INFINITY; lrow[tid] = 0.f; }

    float orow[16];
#pragma unroll
    for (int j = 0; j < 16; j++) orow[j] = 0.f;
    __syncthreads();

    const int kmax = 2 * qb + 1;
    for (int kb = 0; kb <= kmax; kb++) {
        const int k0 = kb * 64;

        // ---- load K, V (single fp16): 64 rows x 64 cols each ----
        {
            const int kr = tid >> 3;
            const int kc = (tid & 7) * 8;
            const size_t g = base + (size_t)(k0 + kr) * D_MODEL + kc;
            *(uint4*)(Kh + kr * LDH + kc) = *(const uint4*)(Kh_g + g);
            *(uint4*)(Vh + kr * LDH + kc) = *(const uint4*)(Vh_g + g);
        }
        __syncthreads();

        // ---- S = Q K^T (2 passes) ----
        {
            wmma::fragment<wmma::accumulator, 16, 16, 16, float> accS[2];
#pragma unroll
            for (int i = 0; i < 2; i++) wmma::fill_fragment(accS[i], 0.f);
#pragma unroll
            for (int ks = 0; ks < 64; ks += 16) {
                wmma::fragment<wmma::matrix_a, 16, 16, 16, __half, wmma::row_major> ah[2], al[2];
                wmma::fragment<wmma::matrix_b, 16, 16, 16, __half, wmma::col_major> bh;
#pragma unroll
                for (int i = 0; i < 2; i++) {
                    wmma::load_matrix_sync(ah[i], Qh + (wm + i * 16) * LDH + ks, LDH);
                    wmma::load_matrix_sync(al[i], Ql + (wm + i * 16) * LDH + ks, LDH);
                }
                wmma::load_matrix_sync(bh, Kh + wn * LDH + ks, LDH);
#pragma unroll
                for (int i = 0; i < 2; i++) {
                    wmma::mma_sync(accS[i], ah[i], bh, accS[i]);
                    wmma::mma_sync(accS[i], al[i], bh, accS[i]);
                }
            }
#pragma unroll
            for (int i = 0; i < 2; i++)
                wmma::store_matrix_sync(Sf + (wm + i * 16) * LDF + wn, accS[i], LDF, wmma::mem_row_major);
        }
        __syncthreads();

        // ---- softmax (4 threads/row) + split P fp16 hi/lo ----
        {
            const bool needmask = (k0 + 63 > q0);
            const int qrow = q0 + r;
            float sv[16];
            const float* srow = Sf + r * LDF + c0;
            float mx = -INFINITY;
#pragma unroll
            for (int j = 0; j < 16; j++) {
                float v = srow[j] * 0.125f;
                if (needmask && (k0 + c0 + j) > qrow) v = -INFINITY;
                sv[j] = v;
                mx = fmaxf(mx, v);
            }
            mx = fmaxf(mx, __shfl_xor_sync(0xFFFFFFFFu, mx, 1));
            mx = fmaxf(mx, __shfl_xor_sync(0xFFFFFFFFu, mx, 2));
            const float mold = mrow[r];
            const float mnew = fmaxf(mold, mx);
            float lsum = 0.f;
#pragma unroll
            for (int j = 0; j < 16; j++) {
                float p = __expf(sv[j] - mnew);
                sv[j] = p;
                lsum += p;
            }
            lsum += __shfl_xor_sync(0xFFFFFFFFu, lsum, 1);
            lsum += __shfl_xor_sync(0xFFFFFFFFu, lsum, 2);
#pragma unroll
            for (int j = 0; j < 16; j += 2) {
                uint32_t hv, lv;
                split2h(sv[j], sv[j + 1], hv, lv);
                *(uint32_t*)(Ph + r * LDH + c0 + j) = hv;
                *(uint32_t*)(Pl + r * LDH + c0 + j) = lv;
            }
            if ((tid & 3) == 0) {
                const float corr = __expf(mold - mnew);
                mrow[r] = mnew;
                lrow[r] = lrow[r] * corr + lsum;
                crow[r] = corr;
            }
        }
        __syncthreads();

        // ---- PV = P @ V (2 passes) -> Sf ----
        {
            wmma::fragment<wmma::accumulator, 16, 16, 16, float> accO[2];
#pragma unroll
            for (int i = 0; i < 2; i++) wmma::fill_fragment(accO[i], 0.f);
#pragma unroll
            for (int ks = 0; ks < 64; ks += 16) {
                wmma::fragment<wmma::matrix_a, 16, 16, 16, __half, wmma::row_major> ah[2], al[2];
                wmma::fragment<wmma::matrix_b, 16, 16, 16, __half, wmma::row_major> bh;
#pragma unroll
                for (int i = 0; i < 2; i++) {
                    wmma::load_matrix_sync(ah[i], Ph + (wm + i * 16) * LDH + ks, LDH);
                    wmma::load_matrix_sync(al[i], Pl + (wm + i * 16) * LDH + ks, LDH);
                }
                wmma::load_matrix_sync(bh, Vh + ks * LDH + wn, LDH);
#pragma unroll
                for (int i = 0; i < 2; i++) {
                    wmma::mma_sync(accO[i], ah[i], bh, accO[i]);
                    wmma::mma_sync(accO[i], al[i], bh, accO[i]);
                }
            }
#pragma unroll
            for (int i = 0; i < 2; i++)
                wmma::store_matrix_sync(Sf + (wm + i * 16) * LDF + wn, accO[i], LDF, wmma::mem_row_major);
        }
        __syncthreads();

        // ---- O = O*corr + PV ----
        {
            const float corr = crow[r];
            const float* prow = Sf + r * LDF + c0;
#pragma unroll
            for (int j = 0; j < 16; j++) orow[j] = orow[j] * corr + prow[j];
        }
        __syncthreads();
    }

    {
        const float inv = 1.f / lrow[r];
        const size_t g = base + (size_t)(q0 + r) * D_MODEL + c0;
#pragma unroll
        for (int j = 0; j < 16; j += 2) {
            uint32_t hv, lv;
            split2h(orow[j] * inv, orow[j + 1] * inv, hv, lv);
            *(uint32_t*)(Oh_g + g + j) = hv;
            *(uint32_t*)(Ol_g + g + j) = lv;
        }
    }
}

// ---------------- LayerNorm (ddof=1), optional fp16 hi/lo output -------------
template <bool HL>
__global__ __launch_bounds__(256)
void layernorm_k(const float* __restrict__ in, const float* __restrict__ gamma,
                 const float* __restrict__ beta, float* __restrict__ out,
                 __half* __restrict__ oh, __half* __restrict__ ol)
{
    const int row = blockIdx.x;
    const int tid = threadIdx.x;
    const float4 v = ((const float4*)(in + (size_t)row * D_MODEL))[tid];
    float s  = v.x + v.y + v.z + v.w;
    float ss = v.x * v.x + v.y * v.y + v.z * v.z + v.w * v.w;

    __shared__ float rs[8], rss[8];
#pragma unroll
    for (int o = 16; o > 0; o >>= 1) {
        s  += __shfl_down_sync(0xFFFFFFFFu, s, o);
        ss += __shfl_down_sync(0xFFFFFFFFu, ss, o);
    }
    if ((tid & 31) == 0) { rs[tid >> 5] = s; rss[tid >> 5] = ss; }
    __syncthreads();
    float S = 0.f, SS = 0.f;
#pragma unroll
    for (int i = 0; i < 8; i++) { S += rs[i]; SS += rss[i]; }

    const float mean = S * (1.f / (float)D_MODEL);
    const float var  = (SS - (float)D_MODEL * mean * mean) * (1.f / (float)(D_MODEL - 1));
    const float inv  = rsqrtf(var + EPS_LN);

    const float4 g = ((const float4*)gamma)[tid];
    const float4 b = ((const float4*)beta)[tid];
    float4 o;
    o.x = g.x * (v.x - mean) * inv + b.x;
    o.y = g.y * (v.y - mean) * inv + b.y;
    o.z = g.z * (v.z - mean) * inv + b.z;
    o.w = g.w * (v.w - mean) * inv + b.w;
    ((float4*)(out + (size_t)row * D_MODEL))[tid] = o;
    if (HL) {
        uint32_t h01, l01, h23, l23;
        split2h(o.x, o.y, h01, l01);
        split2h(o.z, o.w, h23, l23);
        ((uint2*)(oh + (size_t)row * D_MODEL))[tid] = make_uint2(h01, h23);
        ((uint2*)(ol + (size_t)row * D_MODEL))[tid] = make_uint2(l01, l23);
    }
}

// ---------------- host launcher ---------------------------------------------
extern "C" void kernel_launch(void* const* d_in, const int* in_sizes, int n_in,
                              void* d_out, int out_size)
{
    (void)in_sizes; (void)n_in; (void)out_size;
    const float* x  = (const float*)d_in[0];
    const float* Wq = (const float*)d_in[2];
    const float* Wk = (const float*)d_in[3];
    const float* Wv = (const float*)d_in[4];
    const float* Wo = (const float*)d_in[5];
    const float* W1 = (const float*)d_in[6];
    const float* W2 = (const float*)d_in[7];
    const float* g1 = (const float*)d_in[8];
    const float* b1 = (const float*)d_in[9];
    const float* g2 = (const float*)d_in[10];
    const float* b2 = (const float*)d_in[11];
    float* out = (float*)d_out;

    __half *xh, *xl, *wqh, *wkh, *wvh, *woh, *w1h, *w2h;
    __half *qh, *ql, *kh, *kl, *vh, *vl, *ah, *al, *r1h, *r1l, *ffh, *ffl;
    float *tmp, *r1f, *tmp2;
    cudaGetSymbolAddress((void**)&xh, g_xh);   cudaGetSymbolAddress((void**)&xl, g_xl);
    cudaGetSymbolAddress((void**)&wqh, g_wqh); cudaGetSymbolAddress((void**)&wkh, g_wkh);
    cudaGetSymbolAddress((void**)&wvh, g_wvh); cudaGetSymbolAddress((void**)&woh, g_woh);
    cudaGetSymbolAddress((void**)&w1h, g_w1h); cudaGetSymbolAddress((void**)&w2h, g_w2h);
    cudaGetSymbolAddress((void**)&qh, g_qh);   cudaGetSymbolAddress((void**)&ql, g_ql);
    cudaGetSymbolAddress((void**)&kh, g_kh);   cudaGetSymbolAddress((void**)&kl, g_kl);
    cudaGetSymbolAddress((void**)&vh, g_vh);   cudaGetSymbolAddress((void**)&vl, g_vl);
    cudaGetSymbolAddress((void**)&ah, g_ah);   cudaGetSymbolAddress((void**)&al, g_al);
    cudaGetSymbolAddress((void**)&r1h, g_r1h); cudaGetSymbolAddress((void**)&r1l, g_r1l);
    cudaGetSymbolAddress((void**)&ffh, g_ffh); cudaGetSymbolAddress((void**)&ffl, g_ffl);
    cudaGetSymbolAddress((void**)&tmp, g_tmp);
    cudaGetSymbolAddress((void**)&r1f, g_r1f);
    cudaGetSymbolAddress((void**)&tmp2, g_tmp2);

    cudaFuncSetAttribute(gemm_fp16<0,2,1>, cudaFuncAttributeMaxDynamicSharedMemorySize, GEMM_SMEM);
    cudaFuncSetAttribute(gemm_fp16<1,2,0>, cudaFuncAttributeMaxDynamicSharedMemorySize, GEMM_SMEM);
    cudaFuncSetAttribute(gemm_fp16<2,0,0>, cudaFuncAttributeMaxDynamicSharedMemorySize, GEMM_SMEM);
    cudaFuncSetAttribute(flash_fp16, cudaFuncAttributeMaxDynamicSharedMemorySize, FA_SMEM);

    const dim3 blk(256);

    // ---- conversion passes ----
    cvt_hl16<<<NELEM / 4 / 256, blk>>>(x, xh, xl, NELEM / 4);
    cvt_h16<<<WELEM / 4 / 256, blk>>>(Wq, wqh, WELEM / 4);
    cvt_h16<<<WELEM / 4 / 256, blk>>>(Wk, wkh, WELEM / 4);
    cvt_h16<<<WELEM / 4 / 256, blk>>>(Wv, wvh, WELEM / 4);
    cvt_h16<<<WELEM / 4 / 256, blk>>>(Wo, woh, WELEM / 4);
    cvt_h16<<<FELEM / 4 / 256, blk>>>(W1, w1h, FELEM / 4);
    cvt_h16<<<FELEM / 4 / 256, blk>>>(W2, w2h, FELEM / 4);

    const dim3 gQKV(24, MROWS / 128);            // fused QKV
    const dim3 gD(D_MODEL / 128, MROWS / 128);   // (8, 32)
    const dim3 gF(D_FF / 128, MROWS / 128);      // (32, 32)

    // Fused QKV projection -> fp16 hi/lo (flash uses q hi/lo, k/v hi only)
    gemm_fp16<0,2,1><<<gQKV, blk, GEMM_SMEM>>>(xh, xl, wqh, wkh, wvh,
                                               nullptr, nullptr,
                                               qh, ql, kh, kl, vh, vl,
                                               MROWS, D_MODEL, D_MODEL);

    // Flash attention (fp16x2)
    flash_fp16<<<dim3(SEQ / 128, HEADS, BATCH), dim3(512), FA_SMEM>>>(qh, ql, kh, vh, ah, al);

    // Output projection + residual x -> fp32, then LN1 (fp32 + fp16 hi/lo)
    gemm_fp16<2,0,0><<<gD, blk, GEMM_SMEM>>>(ah, al, woh, nullptr, nullptr,
                                             x, tmp,
                                             nullptr, nullptr, nullptr, nullptr, nullptr, nullptr,
                                             MROWS, D_MODEL, D_MODEL);
    layernorm_k<true><<<MROWS, blk>>>(tmp, g1, b1, r1f, r1h, r1l);

    // FFN
    gemm_fp16<1,2,0><<<gF, blk, GEMM_SMEM>>>(r1h, r1l, w1h, nullptr, nullptr,
                                             nullptr, nullptr,
                                             ffh, ffl, nullptr, nullptr, nullptr, nullptr,
                                             MROWS, D_FF, D_MODEL);
    gemm_fp16<2,0,0><<<gD, blk, GEMM_SMEM>>>(ffh, ffl, w2h, nullptr, nullptr,
                                             r1f, tmp2,
                                             nullptr, nullptr, nullptr, nullptr, nullptr, nullptr,
                                             MROWS, D_MODEL, D_FF);
    layernorm_k<false><<<MROWS, blk>>>(tmp2, g2, b2, out, nullptr, nullptr);
}

// round 15
// speedup vs baseline: 2.4930x; 1.5936x over previous
#include <cuda_runtime.h>
#include <cuda_fp16.h>
#include <mma.h>
#include <math.h>
#include <stdint.h>

using namespace nvcuda;

#define D_MODEL 1024
#define HEADS   16
#define DKH     64
#define D_FF    4096
#define BATCH   2
#define SEQ     2048
#define MROWS   (BATCH * SEQ)   // 4096
#define EPS_LN  1e-6f
#define NELEM   (MROWS * D_MODEL)
#define WELEM   (D_MODEL * D_MODEL)
#define FELEM   (D_FF * D_MODEL)
#define FFELEM  (MROWS * D_FF)

// ---------------- scratch (static device globals; no allocs) ----------------
__device__ __half g_xh[NELEM];                         // x fp16
__device__ __half g_wqh[WELEM], g_wkh[WELEM];          // weights fp16
__device__ __half g_wvh[WELEM], g_woh[WELEM];
__device__ __half g_w1h[FELEM], g_w2h[FELEM];
__device__ __half g_qh[NELEM], g_kh[NELEM], g_vh[NELEM];
__device__ __half g_ah[NELEM];                         // attn out fp16
__device__ __half g_r1h[NELEM];                        // LN1 out fp16
__device__ __half g_ffh[FFELEM];                       // relu(ff) fp16
__device__ float g_tmp[NELEM];
__device__ float g_r1f[NELEM];
__device__ float g_tmp2[NELEM];

// ================= helpers ===================================================
#define CP16(dst, src) \
    asm volatile("cp.async.cg.shared.global [%0], [%1], 16;" :: \
        "r"((uint32_t)__cvta_generic_to_shared(dst)), "l"(src))
#define CP_COMMIT() asm volatile("cp.async.commit_group;" ::: "memory")
#define CP_WAIT(n)  asm volatile("cp.async.wait_group %0;" :: "n"(n) : "memory")

// ---------------- fp32 -> fp16 conversion ------------------------------------
__global__ __launch_bounds__(256)
void cvt_h16(const float* __restrict__ src, __half* __restrict__ hi, int n4)
{
    int i = blockIdx.x * 256 + threadIdx.x;
    if (i < n4) {
        float4 v = ((const float4*)src)[i];
        __half2 h01 = __floats2half2_rn(v.x, v.y);
        __half2 h23 = __floats2half2_rn(v.z, v.w);
        ((uint2*)hi)[i] = make_uint2(*(uint32_t*)&h01, *(uint32_t*)&h23);
    }
}

// ================= fp16 GEMM: C = A @ B^T (+epilogue), single pass ===========
// block 128x128, 8 warps (4m x 2n), warp tile 32x64, k-chunk 32, 2 stages.
// EPI: 0 none, 1 relu, 2 residual. OUT: 0 fp32, 2 fp16. QKV: fused 3-dest.
#define GLDT    40
#define GTILE   (128 * GLDT)                 // 5120 halves
#define GSTAGE  (2 * GTILE)                  // Ah, Bh
#define GEMM_SMEM 67584                      // max(2*GSTAGE*2=40960, 128*132*4)

__device__ __forceinline__ void gemm_issue(__half* st,
    const __half* Ahg, const __half* Bhg, int K, int k0, int tid)
{
    __half* sAh = st;
    __half* sBh = st + GTILE;
#pragma unroll
    for (int it = 0; it < 2; it++) {
        int ch = tid + it * 256;          // 0..511
        int r = ch >> 2;                  // 0..127
        int c = (ch & 3) * 8;             // 0..24
        CP16(sAh + r * GLDT + c, Ahg + (size_t)r * K + k0 + c);
        CP16(sBh + r * GLDT + c, Bhg + (size_t)r * K + k0 + c);
    }
}

template <int EPI, int OUT, int QKV>
__global__ __launch_bounds__(256, 2)
void gemm_fp16(const __half* __restrict__ Ah,
               const __half* __restrict__ Bh1, const __half* __restrict__ Bh2,
               const __half* __restrict__ Bh3,
               const float* __restrict__ Rf, float* __restrict__ Cf,
               __half* __restrict__ Hh1, __half* __restrict__ Hh2,
               __half* __restrict__ Hh3,
               int M, int N, int K)
{
    extern __shared__ __half sh[];

    const int tid = threadIdx.x;
    const int wid = tid >> 5;
    const int wm = (wid & 3) * 32;
    const int wn = (wid >> 2) * 64;

    const __half* Bh = Bh1;
    __half* Hh = Hh1;
    int col0;
    if (QKV) {
        const int mat = blockIdx.x >> 3;      // 0,1,2 -> q,k,v
        col0 = (blockIdx.x & 7) * 128;
        if (mat == 1) { Bh = Bh2; Hh = Hh2; }
        else if (mat == 2) { Bh = Bh3; Hh = Hh3; }
    } else {
        col0 = blockIdx.x * 128;
    }
    const int row0 = blockIdx.y * 128;
    const __half* Ahg = Ah + (size_t)row0 * K;
    const __half* Bhg = Bh + (size_t)col0 * K;

    wmma::fragment<wmma::accumulator, 16, 16, 16, float> acc[2][4];
#pragma unroll
    for (int i = 0; i < 2; i++)
#pragma unroll
        for (int j = 0; j < 4; j++) wmma::fill_fragment(acc[i][j], 0.f);

    const int T = K / 32;
    gemm_issue(sh, Ahg, Bhg, K, 0, tid);
    CP_COMMIT();

    for (int t = 0; t < T; t++) {
        CP_WAIT(0);
        __syncthreads();
        if (t + 1 < T) {
            gemm_issue(sh + ((t + 1) & 1) * GSTAGE, Ahg, Bhg, K, (t + 1) * 32, tid);
            CP_COMMIT();
        }
        __half* Ahs = sh + (t & 1) * GSTAGE;
        __half* Bhs = Ahs + GTILE;
#pragma unroll
        for (int ks = 0; ks < 32; ks += 16) {
            wmma::fragment<wmma::matrix_a, 16, 16, 16, __half, wmma::row_major> a_hi[2];
#pragma unroll
            for (int i = 0; i < 2; i++)
                wmma::load_matrix_sync(a_hi[i], Ahs + (wm + i * 16) * GLDT + ks, GLDT);
#pragma unroll
            for (int j = 0; j < 4; j++) {
                wmma::fragment<wmma::matrix_b, 16, 16, 16, __half, wmma::col_major> b_hi;
                wmma::load_matrix_sync(b_hi, Bhs + (wn + j * 16) * GLDT + ks, GLDT);
#pragma unroll
                for (int i = 0; i < 2; i++)
                    wmma::mma_sync(acc[i][j], a_hi[i], b_hi, acc[i][j]);
            }
        }
        __syncthreads();
    }

    if (OUT == 0) {
#pragma unroll
        for (int i = 0; i < 2; i++) {
#pragma unroll
            for (int j = 0; j < 4; j++) {
                const int row = row0 + wm + i * 16;
                const int col = col0 + wn + j * 16;
                if (EPI == 2) {
                    wmma::fragment<wmma::accumulator, 16, 16, 16, float> rf;
                    wmma::load_matrix_sync(rf, Rf + (size_t)row * N + col, N, wmma::mem_row_major);
#pragma unroll
                    for (int e = 0; e < rf.num_elements; e++) acc[i][j].x[e] += rf.x[e];
                }
                if (EPI == 1) {
#pragma unroll
                    for (int e = 0; e < acc[i][j].num_elements; e++)
                        acc[i][j].x[e] = fmaxf(acc[i][j].x[e], 0.f);
                }
                wmma::store_matrix_sync(Cf + (size_t)row * N + col, acc[i][j], N, wmma::mem_row_major);
            }
        }
    } else {
        // stage fp32 tile in smem, then fp16 store
        float* stg = (float*)sh;              // 128 x 132 fp32 = 67584 B
        __syncthreads();
#pragma unroll
        for (int i = 0; i < 2; i++) {
#pragma unroll
            for (int j = 0; j < 4; j++) {
                if (EPI == 1) {
#pragma unroll
                    for (int e = 0; e < acc[i][j].num_elements; e++)
                        acc[i][j].x[e] = fmaxf(acc[i][j].x[e], 0.f);
                }
                wmma::store_matrix_sync(stg + (wm + i * 16) * 132 + wn + j * 16,
                                        acc[i][j], 132, wmma::mem_row_major);
            }
        }
        __syncthreads();
        const int r = tid >> 1;
        const int cb = (tid & 1) * 64;
#pragma unroll
        for (int j = 0; j < 64; j += 4) {
            float4 v = *(const float4*)(stg + r * 132 + cb + j);
            __half2 h01 = __floats2half2_rn(v.x, v.y);
            __half2 h23 = __floats2half2_rn(v.z, v.w);
            const size_t off = (size_t)(row0 + r) * N + col0 + cb + j;
            *(uint2*)(Hh + off) = make_uint2(*(uint32_t*)&h01, *(uint32_t*)&h23);
        }
    }
}

// ================= fp16 flash attention (fp32 softmax), single pass ==========
// grid: (SEQ/128, HEADS, BATCH), 512 threads = 16 warps (4m x 4n).
#define LDH 72
#define LDF 68
#define FO_QH 0
#define FO_KH (FO_QH + 128 * LDH * 2)     // 18432
#define FO_VH (FO_KH + 64 * LDH * 2)      // 27648
#define FO_PH (FO_VH + 64 * LDH * 2)      // 36864
#define FO_SF (FO_PH + 128 * LDH * 2)     // 55296
#define FO_MR (FO_SF + 128 * LDF * 4)     // 90112
#define FO_LR (FO_MR + 512)
#define FO_CR (FO_LR + 512)
#define FA_SMEM (FO_CR + 512)             // 91648 B

__global__ __launch_bounds__(512)
void flash_fp16(const __half* __restrict__ Qh_g, const __half* __restrict__ Kh_g,
                const __half* __restrict__ Vh_g, __half* __restrict__ Oh_g)
{
    extern __shared__ char fsm[];
    __half* Qh = (__half*)(fsm + FO_QH);
    __half* Kh = (__half*)(fsm + FO_KH);
    __half* Vh = (__half*)(fsm + FO_VH);
    __half* Ph = (__half*)(fsm + FO_PH);
    float* Sf   = (float*)(fsm + FO_SF);
    float* mrow = (float*)(fsm + FO_MR);
    float* lrow = (float*)(fsm + FO_LR);
    float* crow = (float*)(fsm + FO_CR);

    const int qb = gridDim.x - 1 - blockIdx.x;   // heavy q-blocks first
    const int h = blockIdx.y, bb = blockIdx.z;
    const int tid = threadIdx.x;
    const int wid = tid >> 5;
    const int wm = (wid & 3) * 32;
    const int wn = (wid >> 2) * 16;
    const int q0 = qb * 128;
    const size_t base = (size_t)bb * SEQ * D_MODEL + (size_t)h * DKH;

    const int r  = tid >> 2;
    const int c0 = (tid & 3) * 16;

    {
        const size_t g = base + (size_t)(q0 + r) * D_MODEL + c0;
        *(uint4*)(Qh + r * LDH + c0)     = *(const uint4*)(Qh_g + g);
        *(uint4*)(Qh + r * LDH + c0 + 8) = *(const uint4*)(Qh_g + g + 8);
    }
    if (tid < 128) { mrow[tid] = -INFINITY; lrow[tid] = 0.f; }

    float orow[16];
#pragma unroll
    for (int j = 0; j < 16; j++) orow[j] = 0.f;
    __syncthreads();

    const int kmax = 2 * qb + 1;
    for (int kb = 0; kb <= kmax; kb++) {
        const int k0 = kb * 64;

        // ---- load K, V ----
        {
            const int kr = tid >> 3;
            const int kc = (tid & 7) * 8;
            const size_t g = base + (size_t)(k0 + kr) * D_MODEL + kc;
            *(uint4*)(Kh + kr * LDH + kc) = *(const uint4*)(Kh_g + g);
            *(uint4*)(Vh + kr * LDH + kc) = *(const uint4*)(Vh_g + g);
        }
        __syncthreads();

        // ---- S = Q K^T ----
        {
            wmma::fragment<wmma::accumulator, 16, 16, 16, float> accS[2];
#pragma unroll
            for (int i = 0; i < 2; i++) wmma::fill_fragment(accS[i], 0.f);
#pragma unroll
            for (int ks = 0; ks < 64; ks += 16) {
                wmma::fragment<wmma::matrix_a, 16, 16, 16, __half, wmma::row_major> ah[2];
                wmma::fragment<wmma::matrix_b, 16, 16, 16, __half, wmma::col_major> bh;
#pragma unroll
                for (int i = 0; i < 2; i++)
                    wmma::load_matrix_sync(ah[i], Qh + (wm + i * 16) * LDH + ks, LDH);
                wmma::load_matrix_sync(bh, Kh + wn * LDH + ks, LDH);
#pragma unroll
                for (int i = 0; i < 2; i++)
                    wmma::mma_sync(accS[i], ah[i], bh, accS[i]);
            }
#pragma unroll
            for (int i = 0; i < 2; i++)
                wmma::store_matrix_sync(Sf + (wm + i * 16) * LDF + wn, accS[i], LDF, wmma::mem_row_major);
        }
        __syncthreads();

        // ---- softmax (4 threads/row), P fp16 ----
        {
            const bool needmask = (k0 + 63 > q0);
            const int qrow = q0 + r;
            float sv[16];
            const float* srow = Sf + r * LDF + c0;
            float mx = -INFINITY;
#pragma unroll
            for (int j = 0; j < 16; j++) {
                float v = srow[j] * 0.125f;
                if (needmask && (k0 + c0 + j) > qrow) v = -INFINITY;
                sv[j] = v;
                mx = fmaxf(mx, v);
            }
            mx = fmaxf(mx, __shfl_xor_sync(0xFFFFFFFFu, mx, 1));
            mx = fmaxf(mx, __shfl_xor_sync(0xFFFFFFFFu, mx, 2));
            const float mold = mrow[r];
            const float mnew = fmaxf(mold, mx);
            float lsum = 0.f;
#pragma unroll
            for (int j = 0; j < 16; j++) {
                float p = __expf(sv[j] - mnew);
                sv[j] = p;
                lsum += p;
            }
            lsum += __shfl_xor_sync(0xFFFFFFFFu, lsum, 1);
            lsum += __shfl_xor_sync(0xFFFFFFFFu, lsum, 2);
#pragma unroll
            for (int j = 0; j < 16; j += 2) {
                __half2 hv = __floats2half2_rn(sv[j], sv[j + 1]);
                *(uint32_t*)(Ph + r * LDH + c0 + j) = *(uint32_t*)&hv;
            }
            if ((tid & 3) == 0) {
                const float corr = __expf(mold - mnew);
                mrow[r] = mnew;
                lrow[r] = lrow[r] * corr + lsum;
                crow[r] = corr;
            }
        }
        __syncthreads();

        // ---- PV = P @ V -> Sf ----
        {
            wmma::fragment<wmma::accumulator, 16, 16, 16, float> accO[2];
#pragma unroll
            for (int i = 0; i < 2; i++) wmma::fill_fragment(accO[i], 0.f);
#pragma unroll
            for (int ks = 0; ks < 64; ks += 16) {
                wmma::fragment<wmma::matrix_a, 16, 16, 16, __half, wmma::row_major> ah[2];
                wmma::fragment<wmma::matrix_b, 16, 16, 16, __half, wmma::row_major> bh;
#pragma unroll
                for (int i = 0; i < 2; i++)
                    wmma::load_matrix_sync(ah[i], Ph + (wm + i * 16) * LDH + ks, LDH);
                wmma::load_matrix_sync(bh, Vh + ks * LDH + wn, LDH);
#pragma unroll
                for (int i = 0; i < 2; i++)
                    wmma::mma_sync(accO[i], ah[i], bh, accO[i]);
            }
#pragma unroll
            for (int i = 0; i < 2; i++)
                wmma::store_matrix_sync(Sf + (wm + i * 16) * LDF + wn, accO[i], LDF, wmma::mem_row_major);
        }
        __syncthreads();

        // ---- O = O*corr + PV ----
        {
            const float corr = crow[r];
            const float* prow = Sf + r * LDF + c0;
#pragma unroll
            for (int j = 0; j < 16; j++) orow[j] = orow[j] * corr + prow[j];
        }
        __syncthreads();
    }

    {
        const float inv = 1.f / lrow[r];
        const size_t g = base + (size_t)(q0 + r) * D_MODEL + c0;
#pragma unroll
        for (int j = 0; j < 16; j += 2) {
            __half2 hv = __floats2half2_rn(orow[j] * inv, orow[j + 1] * inv);
            *(uint32_t*)(Oh_g + g + j) = *(uint32_t*)&hv;
        }
    }
}

// ---------------- LayerNorm (ddof=1), optional fp16 output -------------------
template <bool HL>
__global__ __launch_bounds__(256)
void layernorm_k(const float* __restrict__ in, const float* __restrict__ gamma,
                 const float* __restrict__ beta, float* __restrict__ out,
                 __half* __restrict__ oh)
{
    const int row = blockIdx.x;
    const int tid = threadIdx.x;
    const float4 v = ((const float4*)(in + (size_t)row * D_MODEL))[tid];
    float s  = v.x + v.y + v.z + v.w;
    float ss = v.x * v.x + v.y * v.y + v.z * v.z + v.w * v.w;

    __shared__ float rs[8], rss[8];
#pragma unroll
    for (int o = 16; o > 0; o >>= 1) {
        s  += __shfl_down_sync(0xFFFFFFFFu, s, o);
        ss += __shfl_down_sync(0xFFFFFFFFu, ss, o);
    }
    if ((tid & 31) == 0) { rs[tid >> 5] = s; rss[tid >> 5] = ss; }
    __syncthreads();
    float S = 0.f, SS = 0.f;
#pragma unroll
    for (int i = 0; i < 8; i++) { S += rs[i]; SS += rss[i]; }

    const float mean = S * (1.f / (float)D_MODEL);
    const float var  = (SS - (float)D_MODEL * mean * mean) * (1.f / (float)(D_MODEL - 1));
    const float inv  = rsqrtf(var + EPS_LN);

    const float4 g = ((const float4*)gamma)[tid];
    const float4 b = ((const float4*)beta)[tid];
    float4 o;
    o.x = g.x * (v.x - mean) * inv + b.x;
    o.y = g.y * (v.y - mean) * inv + b.y;
    o.z = g.z * (v.z - mean) * inv + b.z;
    o.w = g.w * (v.w - mean) * inv + b.w;
    ((float4*)(out + (size_t)row * D_MODEL))[tid] = o;
    if (HL) {
        __half2 h01 = __floats2half2_rn(o.x, o.y);
        __half2 h23 = __floats2half2_rn(o.z, o.w);
        ((uint2*)(oh + (size_t)row * D_MODEL))[tid] =
            make_uint2(*(uint32_t*)&h01, *(uint32_t*)&h23);
    }
}

// ---------------- host launcher ---------------------------------------------
extern "C" void kernel_launch(void* const* d_in, const int* in_sizes, int n_in,
                              void* d_out, int out_size)
{
    (void)in_sizes; (void)n_in; (void)out_size;
    const float* x  = (const float*)d_in[0];
    const float* Wq = (const float*)d_in[2];
    const float* Wk = (const float*)d_in[3];
    const float* Wv = (const float*)d_in[4];
    const float* Wo = (const float*)d_in[5];
    const float* W1 = (const float*)d_in[6];
    const float* W2 = (const float*)d_in[7];
    const float* g1 = (const float*)d_in[8];
    const float* b1 = (const float*)d_in[9];
    const float* g2 = (const float*)d_in[10];
    const float* b2 = (const float*)d_in[11];
    float* out = (float*)d_out;

    __half *xh, *wqh, *wkh, *wvh, *woh, *w1h, *w2h;
    __half *qh, *kh, *vh, *ah, *r1h, *ffh;
    float *tmp, *r1f, *tmp2;
    cudaGetSymbolAddress((void**)&xh, g_xh);
    cudaGetSymbolAddress((void**)&wqh, g_wqh); cudaGetSymbolAddress((void**)&wkh, g_wkh);
    cudaGetSymbolAddress((void**)&wvh, g_wvh); cudaGetSymbolAddress((void**)&woh, g_woh);
    cudaGetSymbolAddress((void**)&w1h, g_w1h); cudaGetSymbolAddress((void**)&w2h, g_w2h);
    cudaGetSymbolAddress((void**)&qh, g_qh);   cudaGetSymbolAddress((void**)&kh, g_kh);
    cudaGetSymbolAddress((void**)&vh, g_vh);   cudaGetSymbolAddress((void**)&ah, g_ah);
    cudaGetSymbolAddress((void**)&r1h, g_r1h); cudaGetSymbolAddress((void**)&ffh, g_ffh);
    cudaGetSymbolAddress((void**)&tmp, g_tmp);
    cudaGetSymbolAddress((void**)&r1f, g_r1f);
    cudaGetSymbolAddress((void**)&tmp2, g_tmp2);

    cudaFuncSetAttribute(gemm_fp16<0,2,1>, cudaFuncAttributeMaxDynamicSharedMemorySize, GEMM_SMEM);
    cudaFuncSetAttribute(gemm_fp16<1,2,0>, cudaFuncAttributeMaxDynamicSharedMemorySize, GEMM_SMEM);
    cudaFuncSetAttribute(gemm_fp16<2,0,0>, cudaFuncAttributeMaxDynamicSharedMemorySize, GEMM_SMEM);
    cudaFuncSetAttribute(flash_fp16, cudaFuncAttributeMaxDynamicSharedMemorySize, FA_SMEM);

    const dim3 blk(256);

    // ---- conversion passes ----
    cvt_h16<<<NELEM / 4 / 256, blk>>>(x,  xh,  NELEM / 4);
    cvt_h16<<<WELEM / 4 / 256, blk>>>(Wq, wqh, WELEM / 4);
    cvt_h16<<<WELEM / 4 / 256, blk>>>(Wk, wkh, WELEM / 4);
    cvt_h16<<<WELEM / 4 / 256, blk>>>(Wv, wvh, WELEM / 4);
    cvt_h16<<<WELEM / 4 / 256, blk>>>(Wo, woh, WELEM / 4);
    cvt_h16<<<FELEM / 4 / 256, blk>>>(W1, w1h, FELEM / 4);
    cvt_h16<<<FELEM / 4 / 256, blk>>>(W2, w2h, FELEM / 4);

    const dim3 gQKV(24, MROWS / 128);            // fused QKV
    const dim3 gD(D_MODEL / 128, MROWS / 128);   // (8, 32)
    const dim3 gF(D_FF / 128, MROWS / 128);      // (32, 32)

    // Fused QKV projection -> fp16
    gemm_fp16<0,2,1><<<gQKV, blk, GEMM_SMEM>>>(xh, wqh, wkh, wvh,
                                               nullptr, nullptr,
                                               qh, kh, vh,
                                               MROWS, D_MODEL, D_MODEL);

    // Flash attention (fp16 single-pass)
    flash_fp16<<<dim3(SEQ / 128, HEADS, BATCH), dim3(512), FA_SMEM>>>(qh, kh, vh, ah);

    // Output projection + residual x -> fp32, then LN1 (fp32 + fp16)
    gemm_fp16<2,0,0><<<gD, blk, GEMM_SMEM>>>(ah, woh, nullptr, nullptr,
                                             x, tmp,
                                             nullptr, nullptr, nullptr,
                                             MROWS, D_MODEL, D_MODEL);
    layernorm_k<true><<<MROWS, blk>>>(tmp, g1, b1, r1f, r1h);

    // FFN
    gemm_fp16<1,2,0><<<gF, blk, GEMM_SMEM>>>(r1h, w1h, nullptr, nullptr,
                                             nullptr, nullptr,
                                             ffh, nullptr, nullptr,
                                             MROWS, D_FF, D_MODEL);
    gemm_fp16<2,0,0><<<gD, blk, GEMM_SMEM>>>(ffh, w2h, nullptr, nullptr,
                                             r1f, tmp2,
                                             nullptr, nullptr, nullptr,
                                             MROWS, D_MODEL, D_FF);
    layernorm_k<false><<<MROWS, blk>>>(tmp2, g2, b2, out, nullptr);
}

// round 16
// speedup vs baseline: 3.0837x; 1.2369x over previous
#include <cuda_runtime.h>
#include <cuda_fp16.h>
#include <mma.h>
#include <math.h>
#include <stdint.h>

using namespace nvcuda;

#define D_MODEL 1024
#define HEADS   16
#define DKH     64
#define D_FF    4096
#define BATCH   2
#define SEQ     2048
#define MROWS   (BATCH * SEQ)   // 4096
#define EPS_LN  1e-6f
#define NELEM   (MROWS * D_MODEL)
#define WELEM   (D_MODEL * D_MODEL)
#define FELEM   (D_FF * D_MODEL)
#define FFELEM  (MROWS * D_FF)

// ---------------- scratch (static device globals; no allocs) ----------------
__device__ __half g_xh[NELEM];
__device__ __half g_wqh[WELEM], g_wkh[WELEM];
__device__ __half g_wvh[WELEM], g_woh[WELEM];
__device__ __half g_w1h[FELEM], g_w2h[FELEM];
__device__ __half g_qh[NELEM], g_kh[NELEM], g_vh[NELEM];
__device__ __half g_ah[NELEM];
__device__ __half g_r1h[NELEM];
__device__ __half g_ffh[FFELEM];
__device__ float g_tmp[NELEM];
__device__ float g_r1f[NELEM];
__device__ float g_tmp2[NELEM];

// ================= helpers ===================================================
#define CP16(dst, src) \
    asm volatile("cp.async.cg.shared.global [%0], [%1], 16;" :: \
        "r"((uint32_t)__cvta_generic_to_shared(dst)), "l"(src))
#define CP_COMMIT() asm volatile("cp.async.commit_group;" ::: "memory")
#define CP_WAIT(n)  asm volatile("cp.async.wait_group %0;" :: "n"(n) : "memory")

#define LDSM4(r0, r1, r2, r3, addr) \
    asm volatile("ldmatrix.sync.aligned.m8n8.x4.shared.b16 {%0,%1,%2,%3}, [%4];" \
        : "=r"(r0), "=r"(r1), "=r"(r2), "=r"(r3) : "r"(addr))
#define LDSM4T(r0, r1, r2, r3, addr) \
    asm volatile("ldmatrix.sync.aligned.m8n8.x4.trans.shared.b16 {%0,%1,%2,%3}, [%4];" \
        : "=r"(r0), "=r"(r1), "=r"(r2), "=r"(r3) : "r"(addr))
#define MMA16816(d0, d1, d2, d3, a0, a1, a2, a3, b0, b1) \
    asm volatile("mma.sync.aligned.m16n8k16.row.col.f32.f16.f16.f32 " \
        "{%0,%1,%2,%3}, {%4,%5,%6,%7}, {%8,%9}, {%0,%1,%2,%3};" \
        : "+f"(d0), "+f"(d1), "+f"(d2), "+f"(d3) \
        : "r"(a0), "r"(a1), "r"(a2), "r"(a3), "r"(b0), "r"(b1))

// ---------------- fp32 -> fp16 conversion ------------------------------------
__global__ __launch_bounds__(256)
void cvt_h16(const float* __restrict__ src, __half* __restrict__ hi, int n4)
{
    int i = blockIdx.x * 256 + threadIdx.x;
    if (i < n4) {
        float4 v = ((const float4*)src)[i];
        __half2 h01 = __floats2half2_rn(v.x, v.y);
        __half2 h23 = __floats2half2_rn(v.z, v.w);
        ((uint2*)hi)[i] = make_uint2(*(uint32_t*)&h01, *(uint32_t*)&h23);
    }
}

// ================= fp16 GEMM (unchanged from R15) ============================
#define GLDT    40
#define GTILE   (128 * GLDT)
#define GSTAGE  (2 * GTILE)
#define GEMM_SMEM 67584

__device__ __forceinline__ void gemm_issue(__half* st,
    const __half* Ahg, const __half* Bhg, int K, int k0, int tid)
{
    __half* sAh = st;
    __half* sBh = st + GTILE;
#pragma unroll
    for (int it = 0; it < 2; it++) {
        int ch = tid + it * 256;
        int r = ch >> 2;
        int c = (ch & 3) * 8;
        CP16(sAh + r * GLDT + c, Ahg + (size_t)r * K + k0 + c);
        CP16(sBh + r * GLDT + c, Bhg + (size_t)r * K + k0 + c);
    }
}

template <int EPI, int OUT, int QKV>
__global__ __launch_bounds__(256, 2)
void gemm_fp16(const __half* __restrict__ Ah,
               const __half* __restrict__ Bh1, const __half* __restrict__ Bh2,
               const __half* __restrict__ Bh3,
               const float* __restrict__ Rf, float* __restrict__ Cf,
               __half* __restrict__ Hh1, __half* __restrict__ Hh2,
               __half* __restrict__ Hh3,
               int M, int N, int K)
{
    extern __shared__ __half sh[];

    const int tid = threadIdx.x;
    const int wid = tid >> 5;
    const int wm = (wid & 3) * 32;
    const int wn = (wid >> 2) * 64;

    const __half* Bh = Bh1;
    __half* Hh = Hh1;
    int col0;
    if (QKV) {
        const int mat = blockIdx.x >> 3;
        col0 = (blockIdx.x & 7) * 128;
        if (mat == 1) { Bh = Bh2; Hh = Hh2; }
        else if (mat == 2) { Bh = Bh3; Hh = Hh3; }
    } else {
        col0 = blockIdx.x * 128;
    }
    const int row0 = blockIdx.y * 128;
    const __half* Ahg = Ah + (size_t)row0 * K;
    const __half* Bhg = Bh + (size_t)col0 * K;

    wmma::fragment<wmma::accumulator, 16, 16, 16, float> acc[2][4];
#pragma unroll
    for (int i = 0; i < 2; i++)
#pragma unroll
        for (int j = 0; j < 4; j++) wmma::fill_fragment(acc[i][j], 0.f);

    const int T = K / 32;
    gemm_issue(sh, Ahg, Bhg, K, 0, tid);
    CP_COMMIT();

    for (int t = 0; t < T; t++) {
        CP_WAIT(0);
        __syncthreads();
        if (t + 1 < T) {
            gemm_issue(sh + ((t + 1) & 1) * GSTAGE, Ahg, Bhg, K, (t + 1) * 32, tid);
            CP_COMMIT();
        }
        __half* Ahs = sh + (t & 1) * GSTAGE;
        __half* Bhs = Ahs + GTILE;
#pragma unroll
        for (int ks = 0; ks < 32; ks += 16) {
            wmma::fragment<wmma::matrix_a, 16, 16, 16, __half, wmma::row_major> a_hi[2];
#pragma unroll
            for (int i = 0; i < 2; i++)
                wmma::load_matrix_sync(a_hi[i], Ahs + (wm + i * 16) * GLDT + ks, GLDT);
#pragma unroll
            for (int j = 0; j < 4; j++) {
                wmma::fragment<wmma::matrix_b, 16, 16, 16, __half, wmma::col_major> b_hi;
                wmma::load_matrix_sync(b_hi, Bhs + (wn + j * 16) * GLDT + ks, GLDT);
#pragma unroll
                for (int i = 0; i < 2; i++)
                    wmma::mma_sync(acc[i][j], a_hi[i], b_hi, acc[i][j]);
            }
        }
        __syncthreads();
    }

    if (OUT == 0) {
#pragma unroll
        for (int i = 0; i < 2; i++) {
#pragma unroll
            for (int j = 0; j < 4; j++) {
                const int row = row0 + wm + i * 16;
                const int col = col0 + wn + j * 16;
                if (EPI == 2) {
                    wmma::fragment<wmma::accumulator, 16, 16, 16, float> rf;
                    wmma::load_matrix_sync(rf, Rf + (size_t)row * N + col, N, wmma::mem_row_major);
#pragma unroll
                    for (int e = 0; e < rf.num_elements; e++) acc[i][j].x[e] += rf.x[e];
                }
                if (EPI == 1) {
#pragma unroll
                    for (int e = 0; e < acc[i][j].num_elements; e++)
                        acc[i][j].x[e] = fmaxf(acc[i][j].x[e], 0.f);
                }
                wmma::store_matrix_sync(Cf + (size_t)row * N + col, acc[i][j], N, wmma::mem_row_major);
            }
        }
    } else {
        float* stg = (float*)sh;
        __syncthreads();
#pragma unroll
        for (int i = 0; i < 2; i++) {
#pragma unroll
            for (int j = 0; j < 4; j++) {
                if (EPI == 1) {
#pragma unroll
                    for (int e = 0; e < acc[i][j].num_elements; e++)
                        acc[i][j].x[e] = fmaxf(acc[i][j].x[e], 0.f);
                }
                wmma::store_matrix_sync(stg + (wm + i * 16) * 132 + wn + j * 16,
                                        acc[i][j], 132, wmma::mem_row_major);
            }
        }
        __syncthreads();
        const int r = tid >> 1;
        const int cb = (tid & 1) * 64;
#pragma unroll
        for (int j = 0; j < 64; j += 4) {
            float4 v = *(const float4*)(stg + r * 132 + cb + j);
            __half2 h01 = __floats2half2_rn(v.x, v.y);
            __half2 h23 = __floats2half2_rn(v.z, v.w);
            const size_t off = (size_t)(row0 + r) * N + col0 + cb + j;
            *(uint2*)(Hh + off) = make_uint2(*(uint32_t*)&h01, *(uint32_t*)&h23);
        }
    }
}

// ================= register-resident flash attention (mma.sync) ==============
// 256 threads = 8 warps; warp w owns q-rows [w*16, w*16+16) x ALL 64 kk-cols.
// Q fragments persistent; S/P/O in registers; softmax warp-local; 1 sync/iter.
#define FLDH 72
#define FK_OFF (128 * FLDH)               // halfs
#define FV_OFF (FK_OFF + 2 * 64 * FLDH)
#define FA_SMEM ((128 * FLDH + 4 * 64 * FLDH) * 2)   // 55296 B

__global__ __launch_bounds__(256, 2)
void flash_reg(const __half* __restrict__ Qg, const __half* __restrict__ Kg,
               const __half* __restrict__ Vg, __half* __restrict__ Og)
{
    extern __shared__ __half fs[];
    __half* Qs = fs;

    const int qb = gridDim.x - 1 - blockIdx.x;   // heavy q-blocks first
    const int h = blockIdx.y, bb = blockIdx.z;
    const int tid = threadIdx.x;
    const int wid = tid >> 5, lane = tid & 31;
    const int g = lane >> 2, tg = lane & 3;
    const int band = wid * 16;
    const int q0 = qb * 128;
    const size_t base = (size_t)bb * SEQ * D_MODEL + (size_t)h * DKH;

    // ---- prologue: cp.async Q (128x64) + K/V block 0 (64x64 each) ----
#pragma unroll
    for (int it = 0; it < 4; it++) {
        int ch = tid + it * 256;
        int r = ch >> 3, c = (ch & 7) * 8;
        CP16(Qs + r * FLDH + c, Qg + base + (size_t)(q0 + r) * D_MODEL + c);
    }
#pragma unroll
    for (int it = 0; it < 2; it++) {
        int ch = tid + it * 256;
        int r = ch >> 3, c = (ch & 7) * 8;
        CP16(fs + FK_OFF + r * FLDH + c, Kg + base + (size_t)r * D_MODEL + c);
        CP16(fs + FV_OFF + r * FLDH + c, Vg + base + (size_t)r * D_MODEL + c);
    }
    CP_COMMIT();
    CP_WAIT(0);
    __syncthreads();

    // ---- Q fragments (persistent): qa[ks][0..3] ----
    uint32_t qa[4][4];
    {
        const uint32_t qb32 = (uint32_t)__cvta_generic_to_shared(Qs);
        const int i = lane & 7, seg = lane >> 3;
        const int rr = band + i + ((seg & 1) ? 8 : 0);
        const int cc = (seg & 2) ? 8 : 0;
#pragma unroll
        for (int ks = 0; ks < 4; ks++) {
            uint32_t addr = qb32 + (uint32_t)((rr * FLDH + ks * 16 + cc) * 2);
            LDSM4(qa[ks][0], qa[ks][1], qa[ks][2], qa[ks][3], addr);
        }
    }

    float m0 = -1e30f, m1 = -1e30f, l0 = 0.f, l1 = 0.f;
    float o[8][4];
#pragma unroll
    for (int dt = 0; dt < 8; dt++)
#pragma unroll
        for (int e = 0; e < 4; e++) o[dt][e] = 0.f;

    const int kmax = 2 * qb + 1;
    for (int kb = 0; kb <= kmax; kb++) {
        const int cur = kb & 1;
        // prefetch next K/V into other buffer (safe: sync at end of prev iter)
        if (kb + 1 <= kmax) {
            const int nxt = cur ^ 1;
            const int k0n = (kb + 1) * 64;
#pragma unroll
            for (int it = 0; it < 2; it++) {
                int ch = tid + it * 256;
                int r = ch >> 3, c = (ch & 7) * 8;
                CP16(fs + FK_OFF + nxt * 64 * FLDH + r * FLDH + c,
                     Kg + base + (size_t)(k0n + r) * D_MODEL + c);
                CP16(fs + FV_OFF + nxt * 64 * FLDH + r * FLDH + c,
                     Vg + base + (size_t)(k0n + r) * D_MODEL + c);
            }
            CP_COMMIT();
        }
        const int k0 = kb * 64;

        // ---- S = Q K^T : s[nt][e], nt = kk-tile (8 wide) ----
        float s[8][4];
#pragma unroll
        for (int nt = 0; nt < 8; nt++)
#pragma unroll
            for (int e = 0; e < 4; e++) s[nt][e] = 0.f;
        {
            const uint32_t kb32 = (uint32_t)__cvta_generic_to_shared(fs + FK_OFF + cur * 64 * FLDH);
            const int i = lane & 7, seg = lane >> 3;
            const int rr = i + ((seg & 2) ? 8 : 0);
            const int cc = (seg & 1) ? 8 : 0;
#pragma unroll
            for (int ks = 0; ks < 4; ks++) {
#pragma unroll
                for (int p = 0; p < 4; p++) {
                    uint32_t b0, b1, b2, b3;
                    uint32_t addr = kb32 + (uint32_t)(((p * 16 + rr) * FLDH + ks * 16 + cc) * 2);
                    LDSM4(b0, b1, b2, b3, addr);
                    MMA16816(s[2 * p][0], s[2 * p][1], s[2 * p][2], s[2 * p][3],
                             qa[ks][0], qa[ks][1], qa[ks][2], qa[ks][3], b0, b1);
                    MMA16816(s[2 * p + 1][0], s[2 * p + 1][1], s[2 * p + 1][2], s[2 * p + 1][3],
                             qa[ks][0], qa[ks][1], qa[ks][2], qa[ks][3], b2, b3);
                }
            }
        }

        // ---- softmax (warp-local) + P fragments ----
        uint32_t pa[4][4];
        {
            const bool needmask = (kb >= 2 * qb);
            const int row0 = q0 + band + g;
            const int row1 = row0 + 8;
            float mx0 = -1e30f, mx1 = -1e30f;
#pragma unroll
            for (int nt = 0; nt < 8; nt++) {
                float v0 = s[nt][0] * 0.125f, v1 = s[nt][1] * 0.125f;
                float v2 = s[nt][2] * 0.125f, v3 = s[nt][3] * 0.125f;
                if (needmask) {
                    const int col = k0 + nt * 8 + 2 * tg;
                    if (col > row0)     v0 = -1e30f;
                    if (col + 1 > row0) v1 = -1e30f;
                    if (col > row1)     v2 = -1e30f;
                    if (col + 1 > row1) v3 = -1e30f;
                }
                s[nt][0] = v0; s[nt][1] = v1; s[nt][2] = v2; s[nt][3] = v3;
                mx0 = fmaxf(mx0, fmaxf(v0, v1));
                mx1 = fmaxf(mx1, fmaxf(v2, v3));
            }
            mx0 = fmaxf(mx0, __shfl_xor_sync(0xFFFFFFFFu, mx0, 1));
            mx0 = fmaxf(mx0, __shfl_xor_sync(0xFFFFFFFFu, mx0, 2));
            mx1 = fmaxf(mx1, __shfl_xor_sync(0xFFFFFFFFu, mx1, 1));
            mx1 = fmaxf(mx1, __shfl_xor_sync(0xFFFFFFFFu, mx1, 2));
            const float mn0 = fmaxf(m0, mx0), mn1 = fmaxf(m1, mx1);
            const float corr0 = __expf(m0 - mn0), corr1 = __expf(m1 - mn1);
            float ls0 = 0.f, ls1 = 0.f;
#pragma unroll
            for (int nt = 0; nt < 8; nt++) {
                float p0 = __expf(s[nt][0] - mn0), p1 = __expf(s[nt][1] - mn0);
                float p2 = __expf(s[nt][2] - mn1), p3 = __expf(s[nt][3] - mn1);
                ls0 += p0 + p1;
                ls1 += p2 + p3;
                __half2 h01 = __floats2half2_rn(p0, p1);
                __half2 h23 = __floats2half2_rn(p2, p3);
                pa[nt >> 1][(nt & 1) ? 2 : 0] = *(uint32_t*)&h01;
                pa[nt >> 1][(nt & 1) ? 3 : 1] = *(uint32_t*)&h23;
            }
            ls0 += __shfl_xor_sync(0xFFFFFFFFu, ls0, 1);
            ls0 += __shfl_xor_sync(0xFFFFFFFFu, ls0, 2);
            ls1 += __shfl_xor_sync(0xFFFFFFFFu, ls1, 1);
            ls1 += __shfl_xor_sync(0xFFFFFFFFu, ls1, 2);
            l0 = l0 * corr0 + ls0;
            l1 = l1 * corr1 + ls1;
            m0 = mn0; m1 = mn1;
#pragma unroll
            for (int dt = 0; dt < 8; dt++) {
                o[dt][0] *= corr0; o[dt][1] *= corr0;
                o[dt][2] *= corr1; o[dt][3] *= corr1;
            }
        }

        // ---- O += P @ V ----
        {
            const uint32_t vb32 = (uint32_t)__cvta_generic_to_shared(fs + FV_OFF + cur * 64 * FLDH);
            const int i = lane & 7, seg = lane >> 3;
            const int rr = i + ((seg & 1) ? 8 : 0);
            const int cc = (seg & 2) ? 8 : 0;
#pragma unroll
            for (int jp = 0; jp < 4; jp++) {
#pragma unroll
                for (int p = 0; p < 4; p++) {
                    uint32_t b0, b1, b2, b3;
                    uint32_t addr = vb32 + (uint32_t)(((jp * 16 + rr) * FLDH + p * 16 + cc) * 2);
                    LDSM4T(b0, b1, b2, b3, addr);
                    MMA16816(o[2 * p][0], o[2 * p][1], o[2 * p][2], o[2 * p][3],
                             pa[jp][0], pa[jp][1], pa[jp][2], pa[jp][3], b0, b1);
                    MMA16816(o[2 * p + 1][0], o[2 * p + 1][1], o[2 * p + 1][2], o[2 * p + 1][3],
                             pa[jp][0], pa[jp][1], pa[jp][2], pa[jp][3], b2, b3);
                }
            }
        }

        if (kb + 1 <= kmax) {
            CP_WAIT(0);
            __syncthreads();
        }
    }

    // ---- epilogue: normalize, store fp16 ----
    {
        const float inv0 = 1.f / l0, inv1 = 1.f / l1;
        const int row0 = q0 + band + g;
#pragma unroll
        for (int dt = 0; dt < 8; dt++) {
            __half2 h0 = __floats2half2_rn(o[dt][0] * inv0, o[dt][1] * inv0);
            __half2 h1 = __floats2half2_rn(o[dt][2] * inv1, o[dt][3] * inv1);
            *(uint32_t*)(Og + base + (size_t)row0 * D_MODEL + dt * 8 + 2 * tg) = *(uint32_t*)&h0;
            *(uint32_t*)(Og + base + (size_t)(row0 + 8) * D_MODEL + dt * 8 + 2 * tg) = *(uint32_t*)&h1;
        }
    }
}

// ---------------- LayerNorm (ddof=1), optional fp16 output -------------------
template <bool HL>
__global__ __launch_bounds__(256)
void layernorm_k(const float* __restrict__ in, const float* __restrict__ gamma,
                 const float* __restrict__ beta, float* __restrict__ out,
                 __half* __restrict__ oh)
{
    const int row = blockIdx.x;
    const int tid = threadIdx.x;
    const float4 v = ((const float4*)(in + (size_t)row * D_MODEL))[tid];
    float s  = v.x + v.y + v.z + v.w;
    float ss = v.x * v.x + v.y * v.y + v.z * v.z + v.w * v.w;

    __shared__ float rs[8], rss[8];
#pragma unroll
    for (int o = 16; o > 0; o >>= 1) {
        s  += __shfl_down_sync(0xFFFFFFFFu, s, o);
        ss += __shfl_down_sync(0xFFFFFFFFu, ss, o);
    }
    if ((tid & 31) == 0) { rs[tid >> 5] = s; rss[tid >> 5] = ss; }
    __syncthreads();
    float S = 0.f, SS = 0.f;
#pragma unroll
    for (int i = 0; i < 8; i++) { S += rs[i]; SS += rss[i]; }

    const float mean = S * (1.f / (float)D_MODEL);
    const float var  = (SS - (float)D_MODEL * mean * mean) * (1.f / (float)(D_MODEL - 1));
    const float inv  = rsqrtf(var + EPS_LN);

    const float4 g = ((const float4*)gamma)[tid];
    const float4 b = ((const float4*)beta)[tid];
    float4 o;
    o.x = g.x * (v.x - mean) * inv + b.x;
    o.y = g.y * (v.y - mean) * inv + b.y;
    o.z = g.z * (v.z - mean) * inv + b.z;
    o.w = g.w * (v.w - mean) * inv + b.w;
    ((float4*)(out + (size_t)row * D_MODEL))[tid] = o;
    if (HL) {
        __half2 h01 = __floats2half2_rn(o.x, o.y);
        __half2 h23 = __floats2half2_rn(o.z, o.w);
        ((uint2*)(oh + (size_t)row * D_MODEL))[tid] =
            make_uint2(*(uint32_t*)&h01, *(uint32_t*)&h23);
    }
}

// ---------------- host launcher ---------------------------------------------
extern "C" void kernel_launch(void* const* d_in, const int* in_sizes, int n_in,
                              void* d_out, int out_size)
{
    (void)in_sizes; (void)n_in; (void)out_size;
    const float* x  = (const float*)d_in[0];
    const float* Wq = (const float*)d_in[2];
    const float* Wk = (const float*)d_in[3];
    const float* Wv = (const float*)d_in[4];
    const float* Wo = (const float*)d_in[5];
    const float* W1 = (const float*)d_in[6];
    const float* W2 = (const float*)d_in[7];
    const float* g1 = (const float*)d_in[8];
    const float* b1 = (const float*)d_in[9];
    const float* g2 = (const float*)d_in[10];
    const float* b2 = (const float*)d_in[11];
    float* out = (float*)d_out;

    __half *xh, *wqh, *wkh, *wvh, *woh, *w1h, *w2h;
    __half *qh, *kh, *vh, *ah, *r1h, *ffh;
    float *tmp, *r1f, *tmp2;
    cudaGetSymbolAddress((void**)&xh, g_xh);
    cudaGetSymbolAddress((void**)&wqh, g_wqh); cudaGetSymbolAddress((void**)&wkh, g_wkh);
    cudaGetSymbolAddress((void**)&wvh, g_wvh); cudaGetSymbolAddress((void**)&woh, g_woh);
    cudaGetSymbolAddress((void**)&w1h, g_w1h); cudaGetSymbolAddress((void**)&w2h, g_w2h);
    cudaGetSymbolAddress((void**)&qh, g_qh);   cudaGetSymbolAddress((void**)&kh, g_kh);
    cudaGetSymbolAddress((void**)&vh, g_vh);   cudaGetSymbolAddress((void**)&ah, g_ah);
    cudaGetSymbolAddress((void**)&r1h, g_r1h); cudaGetSymbolAddress((void**)&ffh, g_ffh);
    cudaGetSymbolAddress((void**)&tmp, g_tmp);
    cudaGetSymbolAddress((void**)&r1f, g_r1f);
    cudaGetSymbolAddress((void**)&tmp2, g_tmp2);

    cudaFuncSetAttribute(gemm_fp16<0,2,1>, cudaFuncAttributeMaxDynamicSharedMemorySize, GEMM_SMEM);
    cudaFuncSetAttribute(gemm_fp16<1,2,0>, cudaFuncAttributeMaxDynamicSharedMemorySize, GEMM_SMEM);
    cudaFuncSetAttribute(gemm_fp16<2,0,0>, cudaFuncAttributeMaxDynamicSharedMemorySize, GEMM_SMEM);
    cudaFuncSetAttribute(flash_reg, cudaFuncAttributeMaxDynamicSharedMemorySize, FA_SMEM);

    const dim3 blk(256);

    // ---- conversion passes ----
    cvt_h16<<<NELEM / 4 / 256, blk>>>(x,  xh,  NELEM / 4);
    cvt_h16<<<WELEM / 4 / 256, blk>>>(Wq, wqh, WELEM / 4);
    cvt_h16<<<WELEM / 4 / 256, blk>>>(Wk, wkh, WELEM / 4);
    cvt_h16<<<WELEM / 4 / 256, blk>>>(Wv, wvh, WELEM / 4);
    cvt_h16<<<WELEM / 4 / 256, blk>>>(Wo, woh, WELEM / 4);
    cvt_h16<<<FELEM / 4 / 256, blk>>>(W1, w1h, FELEM / 4);
    cvt_h16<<<FELEM / 4 / 256, blk>>>(W2, w2h, FELEM / 4);

    const dim3 gQKV(24, MROWS / 128);
    const dim3 gD(D_MODEL / 128, MROWS / 128);
    const dim3 gF(D_FF / 128, MROWS / 128);

    // Fused QKV projection -> fp16
    gemm_fp16<0,2,1><<<gQKV, blk, GEMM_SMEM>>>(xh, wqh, wkh, wvh,
                                               nullptr, nullptr,
                                               qh, kh, vh,
                                               MROWS, D_MODEL, D_MODEL);

    // Register-resident flash attention
    flash_reg<<<dim3(SEQ / 128, HEADS, BATCH), blk, FA_SMEM>>>(qh, kh, vh, ah);

    // Output projection + residual x -> fp32, then LN1 (fp32 + fp16)
    gemm_fp16<2,0,0><<<gD, blk, GEMM_SMEM>>>(ah, woh, nullptr, nullptr,
                                             x, tmp,
                                             nullptr, nullptr, nullptr,
                                             MROWS, D_MODEL, D_MODEL);
    layernorm_k<true><<<MROWS, blk>>>(tmp, g1, b1, r1f, r1h);

    // FFN
    gemm_fp16<1,2,0><<<gF, blk, GEMM_SMEM>>>(r1h, w1h, nullptr, nullptr,
                                             nullptr, nullptr,
                                             ffh, nullptr, nullptr,
                                             MROWS, D_FF, D_MODEL);
    gemm_fp16<2,0,0><<<gD, blk, GEMM_SMEM>>>(ffh, w2h, nullptr, nullptr,
                                             r1f, tmp2,
                                             nullptr, nullptr, nullptr,
                                             MROWS, D_MODEL, D_FF);
    layernorm_k<false><<<MROWS, blk>>>(tmp2, g2, b2, out, nullptr);
}